// round 2
// baseline (speedup 1.0000x reference)
#include <cuda_runtime.h>
#include <cuda_bf16.h>
#include <cstdint>

// ---------------------------------------------------------------------------
// SimplifiedMambaSSM  (B=8, T=4096, D_MODEL=1024, D_STATE=16)
// Inputs (metadata order):
//  0 x[8,4096,1024] 1 h0[8,16] 2 mask[8,4096] 3 A_diag[16]
//  4 W_delta[16,1024] 5 W_B[16,1024] 6 W_C[16,1024] 7 W_out[1024,16]
//  8 D[1024] 9 W_gate[1024,1024] 10 b_gate[1024] 11 ln_w[1024] 12 ln_b[1024]
// Output: y[8,4096,1024] then h_final[8,16]  (float32)
// ---------------------------------------------------------------------------

#define BB     8
#define TT     4096
#define DM     1024
#define DS     16
#define MM     (BB * TT)          // 32768 tokens
#define LN_EPS 1e-5f

// Scratch (static __device__ arrays: allowed; no runtime allocation)
__device__ float g_gatepre[MM * DM];      // 128 MB
__device__ float g_abc[MM * 3 * DS];      // [M][48]: A_bar | Bt | Ct
__device__ float g_s[MM * DS];            // Ct * h per token

// ---------------------------------------------------------------------------
// fast math helpers
// ---------------------------------------------------------------------------
__device__ __forceinline__ float tanh_fast(float x) {
    float r;
    asm("tanh.approx.f32 %0, %1;" : "=f"(r) : "f"(x));
    return r;
}

__device__ __forceinline__ float sigmoid_fast(float x) {
    return 1.0f / (1.0f + __expf(-x));
}

__device__ __forceinline__ float softplus_fast(float x) {
    if (x > 20.0f) return x;
    return __logf(1.0f + __expf(x));
}

// ---------------------------------------------------------------------------
// Kernel 1: gate_pre = x @ W_gate^T + b_gate        [M,1024] x [1024,1024]
// Classic 128x128x8 tile, 256 threads, 8x8 per-thread microtile.
// ---------------------------------------------------------------------------
#define BM 128
#define BN 128
#define BK 8

__global__ void __launch_bounds__(256)
k_gate_gemm(const float* __restrict__ x, const float* __restrict__ Wg,
            const float* __restrict__ bg, float* __restrict__ gp)
{
    __shared__ float As[BK][BM];
    __shared__ float Bs[BK][BN];

    const int m0 = blockIdx.x * BM;
    const int n0 = blockIdx.y * BN;
    const int tid = threadIdx.x;
    const int ty = tid / 16;          // 0..15 -> row group
    const int tx = tid % 16;          // 0..15 -> col group

    const int lm = tid >> 1;          // 0..127: row within tile
    const int lk = (tid & 1) * 4;     // 0 or 4: k quad

    const float* pA = x  + (size_t)(m0 + lm) * DM + lk;
    const float* pB = Wg + (size_t)(n0 + lm) * DM + lk;

    float acc[8][8];
#pragma unroll
    for (int i = 0; i < 8; i++)
#pragma unroll
        for (int j = 0; j < 8; j++) acc[i][j] = 0.0f;

    for (int k0 = 0; k0 < DM; k0 += BK) {
        float4 a4 = *(const float4*)(pA + k0);
        float4 b4 = *(const float4*)(pB + k0);
        __syncthreads();
        As[lk + 0][lm] = a4.x; As[lk + 1][lm] = a4.y;
        As[lk + 2][lm] = a4.z; As[lk + 3][lm] = a4.w;
        Bs[lk + 0][lm] = b4.x; Bs[lk + 1][lm] = b4.y;
        Bs[lk + 2][lm] = b4.z; Bs[lk + 3][lm] = b4.w;
        __syncthreads();

#pragma unroll
        for (int kk = 0; kk < BK; kk++) {
            float4 a0 = *(const float4*)&As[kk][ty * 8];
            float4 a1 = *(const float4*)&As[kk][ty * 8 + 4];
            float4 b0 = *(const float4*)&Bs[kk][tx * 8];
            float4 b1 = *(const float4*)&Bs[kk][tx * 8 + 4];
            float a[8] = {a0.x, a0.y, a0.z, a0.w, a1.x, a1.y, a1.z, a1.w};
            float b[8] = {b0.x, b0.y, b0.z, b0.w, b1.x, b1.y, b1.z, b1.w};
#pragma unroll
            for (int i = 0; i < 8; i++)
#pragma unroll
                for (int j = 0; j < 8; j++)
                    acc[i][j] = fmaf(a[i], b[j], acc[i][j]);
        }
    }

    // epilogue: + bias, store
    const int nb = n0 + tx * 8;
    float4 bi0 = *(const float4*)(bg + nb);
    float4 bi1 = *(const float4*)(bg + nb + 4);
#pragma unroll
    for (int i = 0; i < 8; i++) {
        const size_t m = (size_t)(m0 + ty * 8 + i);
        float4 r0 = make_float4(acc[i][0] + bi0.x, acc[i][1] + bi0.y,
                                acc[i][2] + bi0.z, acc[i][3] + bi0.w);
        float4 r1 = make_float4(acc[i][4] + bi1.x, acc[i][5] + bi1.y,
                                acc[i][6] + bi1.z, acc[i][7] + bi1.w);
        *(float4*)(gp + m * DM + nb)     = r0;
        *(float4*)(gp + m * DM + nb + 4) = r1;
    }
}

// ---------------------------------------------------------------------------
// Kernel 2: per-token LN + sigmoid + xg, then 48 projections -> A_bar,Bt,Ct
// One block (256 threads) per token.
// ---------------------------------------------------------------------------
__global__ void __launch_bounds__(256)
k_ln_proj(const float* __restrict__ gp, const float* __restrict__ x,
          const float* __restrict__ lnw, const float* __restrict__ lnb,
          const float* __restrict__ Wd, const float* __restrict__ Wb,
          const float* __restrict__ Wc, const float* __restrict__ Adiag,
          float* __restrict__ abc)
{
    __shared__ float sxg[DM];
    __shared__ float red[2][8];
    __shared__ float s_stats[2];

    const int row  = blockIdx.x;
    const int tid  = threadIdx.x;
    const int lane = tid & 31;
    const int warp = tid >> 5;

    const size_t base = (size_t)row * DM;
    float4 gv = *(const float4*)(gp + base + tid * 4);

    float s1 = gv.x + gv.y + gv.z + gv.w;
    float s2 = gv.x*gv.x + gv.y*gv.y + gv.z*gv.z + gv.w*gv.w;
#pragma unroll
    for (int off = 16; off; off >>= 1) {
        s1 += __shfl_down_sync(0xffffffffu, s1, off);
        s2 += __shfl_down_sync(0xffffffffu, s2, off);
    }
    if (lane == 0) { red[0][warp] = s1; red[1][warp] = s2; }
    __syncthreads();
    if (tid == 0) {
        float t1 = 0.f, t2 = 0.f;
#pragma unroll
        for (int w = 0; w < 8; w++) { t1 += red[0][w]; t2 += red[1][w]; }
        float mean = t1 * (1.0f / DM);
        float var  = t2 * (1.0f / DM) - mean * mean;
        s_stats[0] = mean;
        s_stats[1] = rsqrtf(var + LN_EPS);
    }
    __syncthreads();
    const float mean = s_stats[0];
    const float rstd = s_stats[1];

    float4 xv = *(const float4*)(x + base + tid * 4);
    float4 wv = *(const float4*)(lnw + tid * 4);
    float4 bv = *(const float4*)(lnb + tid * 4);
    float4 xg;
    xg.x = xv.x * sigmoid_fast((gv.x - mean) * rstd * wv.x + bv.x);
    xg.y = xv.y * sigmoid_fast((gv.y - mean) * rstd * wv.y + bv.y);
    xg.z = xv.z * sigmoid_fast((gv.z - mean) * rstd * wv.z + bv.z);
    xg.w = xv.w * sigmoid_fast((gv.w - mean) * rstd * wv.w + bv.w);
    *(float4*)&sxg[tid * 4] = xg;
    __syncthreads();

    // 48 projection outputs: warp w handles o = w*6 .. w*6+5
    const int obase = warp * 6;
    float acc[6] = {0.f, 0.f, 0.f, 0.f, 0.f, 0.f};
#pragma unroll
    for (int it = 0; it < 8; it++) {
        const int k = it * 128 + lane * 4;
        float4 xgv = *(const float4*)&sxg[k];
#pragma unroll
        for (int oo = 0; oo < 6; oo++) {
            const int o = obase + oo;
            const float* W = (o < 16) ? (Wd + (size_t)o * DM)
                           : (o < 32) ? (Wb + (size_t)(o - 16) * DM)
                                      : (Wc + (size_t)(o - 32) * DM);
            float4 w4 = *(const float4*)(W + k);
            acc[oo] = fmaf(xgv.x, w4.x, acc[oo]);
            acc[oo] = fmaf(xgv.y, w4.y, acc[oo]);
            acc[oo] = fmaf(xgv.z, w4.z, acc[oo]);
            acc[oo] = fmaf(xgv.w, w4.w, acc[oo]);
        }
    }
#pragma unroll
    for (int oo = 0; oo < 6; oo++) {
#pragma unroll
        for (int off = 16; off; off >>= 1)
            acc[oo] += __shfl_down_sync(0xffffffffu, acc[oo], off);
    }
    if (lane == 0) {
        float* dst = abc + (size_t)row * 48;
#pragma unroll
        for (int oo = 0; oo < 6; oo++) {
            const int o = obase + oo;
            float v = acc[oo];
            if (o < 16) {
                float dlt = softplus_fast(v);
                dst[o] = __expf(dlt * Adiag[o]);    // A_bar
            } else {
                dst[o] = v;                          // Bt (16..31) / Ct (32..47)
            }
        }
    }
}

// ---------------------------------------------------------------------------
// Kernel 3: sequential scan over T, one block per batch.
// warp 0 = consumer (16 chains), warps 1..3 = producers (double-buffered SMEM).
// Emits s = Ct*h per token and h_final.
// ---------------------------------------------------------------------------
#define CH 128
#define NCH (TT / CH)

__global__ void __launch_bounds__(128)
k_scan(const float* __restrict__ abc, const float* __restrict__ mask,
       const float* __restrict__ h0, float* __restrict__ sout,
       float* __restrict__ out, int out_size)
{
    __shared__ float sbuf[2][CH * 48];
    __shared__ float smask[2][CH];

    const int b    = blockIdx.x;
    const int tid  = threadIdx.x;
    const int lane = tid & 31;
    const int warp = tid >> 5;

    const float* abc_b  = abc  + (size_t)b * TT * 48;
    const float* mask_b = mask + (size_t)b * TT;

    // preload chunk 0 with all 128 threads
    {
        const float4* src = (const float4*)abc_b;
        float4* dst = (float4*)sbuf[0];
        for (int i = tid; i < CH * 48 / 4; i += 128) dst[i] = src[i];
        const float4* ms = (const float4*)mask_b;
        float4* md = (float4*)smask[0];
        for (int i = tid; i < CH / 4; i += 128) md[i] = ms[i];
    }
    __syncthreads();

    float h = 0.0f;
    if (warp == 0 && lane < DS) h = h0[b * DS + lane];

    for (int c = 0; c < NCH; c++) {
        const int cur = c & 1;
        if (warp > 0 && c + 1 < NCH) {
            const int tix = tid - 32;             // 0..95
            const float4* src = (const float4*)(abc_b + (size_t)(c + 1) * CH * 48);
            float4* dst = (float4*)sbuf[cur ^ 1];
            for (int i = tix; i < CH * 48 / 4; i += 96) dst[i] = src[i];
            const float4* ms = (const float4*)(mask_b + (size_t)(c + 1) * CH);
            float4* md = (float4*)smask[cur ^ 1];
            for (int i = tix; i < CH / 4; i += 96) md[i] = ms[i];
        }
        if (warp == 0 && lane < DS) {
            const float* buf = sbuf[cur];
            float* sdst = sout + ((size_t)b * TT + (size_t)c * CH) * DS + lane;
#pragma unroll 4
            for (int t = 0; t < CH; t++) {
                const float a  = buf[t * 48 + lane];
                const float bb = buf[t * 48 + 16 + lane];
                const float ct = buf[t * 48 + 32 + lane];
                const float m  = smask[cur][t];
                const float im = 1.0f - m;
                const float hc = tanh_fast(fmaf(a, h, bb));
                h = fmaf(m, hc, im * h);           // m*hc + (1-m)*h
                sdst[(size_t)t * DS] = ct * h;
            }
        }
        __syncthreads();
    }

    if (warp == 0 && lane < DS && out_size >= MM * DM + BB * DS)
        out[(size_t)MM * DM + b * DS + lane] = h;
}

// ---------------------------------------------------------------------------
// Kernel 4: y = D*x + s @ W_out^T.  One block (256 threads) per token; each
// thread produces one float4 of y.
// ---------------------------------------------------------------------------
__global__ void __launch_bounds__(256)
k_out(const float* __restrict__ sv_g, const float* __restrict__ x,
      const float* __restrict__ Wout, const float* __restrict__ Dv,
      float* __restrict__ y)
{
    __shared__ float sv[DS];
    const int row = blockIdx.x;
    const int tid = threadIdx.x;

    if (tid < DS) sv[tid] = sv_g[(size_t)row * DS + tid];
    __syncthreads();

    const int d = tid * 4;
    const size_t base = (size_t)row * DM + d;
    float4 xv = *(const float4*)(x + base);
    float4 dd = *(const float4*)(Dv + d);

    float ys[4] = {0.f, 0.f, 0.f, 0.f};
#pragma unroll
    for (int r = 0; r < 4; r++) {
        const float* wrow = Wout + (size_t)(d + r) * DS;
#pragma unroll
        for (int s4 = 0; s4 < DS; s4 += 4) {
            float4 w4 = *(const float4*)(wrow + s4);
            ys[r] = fmaf(sv[s4 + 0], w4.x, ys[r]);
            ys[r] = fmaf(sv[s4 + 1], w4.y, ys[r]);
            ys[r] = fmaf(sv[s4 + 2], w4.z, ys[r]);
            ys[r] = fmaf(sv[s4 + 3], w4.w, ys[r]);
        }
    }
    float4 out4 = make_float4(ys[0] + dd.x * xv.x, ys[1] + dd.y * xv.y,
                              ys[2] + dd.z * xv.z, ys[3] + dd.w * xv.w);
    *(float4*)(y + base) = out4;
}

// ---------------------------------------------------------------------------
extern "C" void kernel_launch(void* const* d_in, const int* in_sizes, int n_in,
                              void* d_out, int out_size)
{
    const float* x      = (const float*)d_in[0];
    const float* h0     = (const float*)d_in[1];
    const float* mask   = (const float*)d_in[2];
    const float* A_diag = (const float*)d_in[3];
    const float* W_del  = (const float*)d_in[4];
    const float* W_B    = (const float*)d_in[5];
    const float* W_C    = (const float*)d_in[6];
    const float* W_out  = (const float*)d_in[7];
    const float* Dv     = (const float*)d_in[8];
    const float* W_gate = (const float*)d_in[9];
    const float* b_gate = (const float*)d_in[10];
    const float* ln_w   = (const float*)d_in[11];
    const float* ln_b   = (const float*)d_in[12];
    float* out = (float*)d_out;

    float* gp;  cudaGetSymbolAddress((void**)&gp,  g_gatepre);
    float* abc; cudaGetSymbolAddress((void**)&abc, g_abc);
    float* sg;  cudaGetSymbolAddress((void**)&sg,  g_s);

    dim3 g1(MM / BM, DM / BN);
    k_gate_gemm<<<g1, 256>>>(x, W_gate, b_gate, gp);

    k_ln_proj<<<MM, 256>>>(gp, x, ln_w, ln_b, W_del, W_B, W_C, A_diag, abc);

    k_scan<<<BB, 128>>>(abc, mask, h0, sg, out, out_size);

    k_out<<<MM, 256>>>(sg, x, W_out, Dv, out);
}

// round 3
// speedup vs baseline: 1.0001x; 1.0001x over previous
#include <cuda_runtime.h>
#include <cuda_bf16.h>
#include <cstdint>

// ---------------------------------------------------------------------------
// SimplifiedMambaSSM  (B=8, T=4096, D_MODEL=1024, D_STATE=16)
// Inputs (metadata order):
//  0 x[8,4096,1024] 1 h0[8,16] 2 mask[8,4096] 3 A_diag[16]
//  4 W_delta[16,1024] 5 W_B[16,1024] 6 W_C[16,1024] 7 W_out[1024,16]
//  8 D[1024] 9 W_gate[1024,1024] 10 b_gate[1024] 11 ln_w[1024] 12 ln_b[1024]
// Output: y[8,4096,1024] then h_final[8,16]  (float32)
// ---------------------------------------------------------------------------

#define BB     8
#define TT     4096
#define DM     1024
#define DS     16
#define MM     (BB * TT)          // 32768 tokens
#define LN_EPS 1e-5f

// Scratch (static __device__ arrays: allowed; no runtime allocation)
__device__ float g_gatepre[MM * DM];      // 128 MB
__device__ float g_abc[MM * 3 * DS];      // [M][48]: A_bar | Bt | Ct
__device__ float g_s[MM * DS];            // Ct * h per token

// ---------------------------------------------------------------------------
// fast math helpers
// ---------------------------------------------------------------------------
__device__ __forceinline__ float tanh_fast(float x) {
    float r;
    asm("tanh.approx.f32 %0, %1;" : "=f"(r) : "f"(x));
    return r;
}

__device__ __forceinline__ float sigmoid_fast(float x) {
    return 1.0f / (1.0f + __expf(-x));
}

__device__ __forceinline__ float softplus_fast(float x) {
    if (x > 20.0f) return x;
    return __logf(1.0f + __expf(x));
}

// ---------------------------------------------------------------------------
// Kernel 1: gate_pre = x @ W_gate^T + b_gate        [M,1024] x [1024,1024]
// Classic 128x128x8 tile, 256 threads, 8x8 per-thread microtile.
// ---------------------------------------------------------------------------
#define BM 128
#define BN 128
#define BK 8

__global__ void __launch_bounds__(256)
k_gate_gemm(const float* __restrict__ x, const float* __restrict__ Wg,
            const float* __restrict__ bg, float* __restrict__ gp)
{
    __shared__ float As[BK][BM];
    __shared__ float Bs[BK][BN];

    const int m0 = blockIdx.x * BM;
    const int n0 = blockIdx.y * BN;
    const int tid = threadIdx.x;
    const int ty = tid / 16;          // 0..15 -> row group
    const int tx = tid % 16;          // 0..15 -> col group

    const int lm = tid >> 1;          // 0..127: row within tile
    const int lk = (tid & 1) * 4;     // 0 or 4: k quad

    const float* pA = x  + (size_t)(m0 + lm) * DM + lk;
    const float* pB = Wg + (size_t)(n0 + lm) * DM + lk;

    float acc[8][8];
#pragma unroll
    for (int i = 0; i < 8; i++)
#pragma unroll
        for (int j = 0; j < 8; j++) acc[i][j] = 0.0f;

    for (int k0 = 0; k0 < DM; k0 += BK) {
        float4 a4 = *(const float4*)(pA + k0);
        float4 b4 = *(const float4*)(pB + k0);
        __syncthreads();
        As[lk + 0][lm] = a4.x; As[lk + 1][lm] = a4.y;
        As[lk + 2][lm] = a4.z; As[lk + 3][lm] = a4.w;
        Bs[lk + 0][lm] = b4.x; Bs[lk + 1][lm] = b4.y;
        Bs[lk + 2][lm] = b4.z; Bs[lk + 3][lm] = b4.w;
        __syncthreads();

#pragma unroll
        for (int kk = 0; kk < BK; kk++) {
            float4 a0 = *(const float4*)&As[kk][ty * 8];
            float4 a1 = *(const float4*)&As[kk][ty * 8 + 4];
            float4 b0 = *(const float4*)&Bs[kk][tx * 8];
            float4 b1 = *(const float4*)&Bs[kk][tx * 8 + 4];
            float a[8] = {a0.x, a0.y, a0.z, a0.w, a1.x, a1.y, a1.z, a1.w};
            float b[8] = {b0.x, b0.y, b0.z, b0.w, b1.x, b1.y, b1.z, b1.w};
#pragma unroll
            for (int i = 0; i < 8; i++)
#pragma unroll
                for (int j = 0; j < 8; j++)
                    acc[i][j] = fmaf(a[i], b[j], acc[i][j]);
        }
    }

    // epilogue: + bias, store
    const int nb = n0 + tx * 8;
    float4 bi0 = *(const float4*)(bg + nb);
    float4 bi1 = *(const float4*)(bg + nb + 4);
#pragma unroll
    for (int i = 0; i < 8; i++) {
        const size_t m = (size_t)(m0 + ty * 8 + i);
        float4 r0 = make_float4(acc[i][0] + bi0.x, acc[i][1] + bi0.y,
                                acc[i][2] + bi0.z, acc[i][3] + bi0.w);
        float4 r1 = make_float4(acc[i][4] + bi1.x, acc[i][5] + bi1.y,
                                acc[i][6] + bi1.z, acc[i][7] + bi1.w);
        *(float4*)(gp + m * DM + nb)     = r0;
        *(float4*)(gp + m * DM + nb + 4) = r1;
    }
}

// ---------------------------------------------------------------------------
// Kernel 2: per-token LN + sigmoid + xg, then 48 projections -> A_bar,Bt,Ct
// One block (256 threads) per token.
// ---------------------------------------------------------------------------
__global__ void __launch_bounds__(256)
k_ln_proj(const float* __restrict__ gp, const float* __restrict__ x,
          const float* __restrict__ lnw, const float* __restrict__ lnb,
          const float* __restrict__ Wd, const float* __restrict__ Wb,
          const float* __restrict__ Wc, const float* __restrict__ Adiag,
          float* __restrict__ abc)
{
    __shared__ float sxg[DM];
    __shared__ float red[2][8];
    __shared__ float s_stats[2];

    const int row  = blockIdx.x;
    const int tid  = threadIdx.x;
    const int lane = tid & 31;
    const int warp = tid >> 5;

    const size_t base = (size_t)row * DM;
    float4 gv = *(const float4*)(gp + base + tid * 4);

    float s1 = gv.x + gv.y + gv.z + gv.w;
    float s2 = gv.x*gv.x + gv.y*gv.y + gv.z*gv.z + gv.w*gv.w;
#pragma unroll
    for (int off = 16; off; off >>= 1) {
        s1 += __shfl_down_sync(0xffffffffu, s1, off);
        s2 += __shfl_down_sync(0xffffffffu, s2, off);
    }
    if (lane == 0) { red[0][warp] = s1; red[1][warp] = s2; }
    __syncthreads();
    if (tid == 0) {
        float t1 = 0.f, t2 = 0.f;
#pragma unroll
        for (int w = 0; w < 8; w++) { t1 += red[0][w]; t2 += red[1][w]; }
        float mean = t1 * (1.0f / DM);
        float var  = t2 * (1.0f / DM) - mean * mean;
        s_stats[0] = mean;
        s_stats[1] = rsqrtf(var + LN_EPS);
    }
    __syncthreads();
    const float mean = s_stats[0];
    const float rstd = s_stats[1];

    float4 xv = *(const float4*)(x + base + tid * 4);
    float4 wv = *(const float4*)(lnw + tid * 4);
    float4 bv = *(const float4*)(lnb + tid * 4);
    float4 xg;
    xg.x = xv.x * sigmoid_fast((gv.x - mean) * rstd * wv.x + bv.x);
    xg.y = xv.y * sigmoid_fast((gv.y - mean) * rstd * wv.y + bv.y);
    xg.z = xv.z * sigmoid_fast((gv.z - mean) * rstd * wv.z + bv.z);
    xg.w = xv.w * sigmoid_fast((gv.w - mean) * rstd * wv.w + bv.w);
    *(float4*)&sxg[tid * 4] = xg;
    __syncthreads();

    // 48 projection outputs: warp w handles o = w*6 .. w*6+5
    const int obase = warp * 6;
    float acc[6] = {0.f, 0.f, 0.f, 0.f, 0.f, 0.f};
#pragma unroll
    for (int it = 0; it < 8; it++) {
        const int k = it * 128 + lane * 4;
        float4 xgv = *(const float4*)&sxg[k];
#pragma unroll
        for (int oo = 0; oo < 6; oo++) {
            const int o = obase + oo;
            const float* W = (o < 16) ? (Wd + (size_t)o * DM)
                           : (o < 32) ? (Wb + (size_t)(o - 16) * DM)
                                      : (Wc + (size_t)(o - 32) * DM);
            float4 w4 = *(const float4*)(W + k);
            acc[oo] = fmaf(xgv.x, w4.x, acc[oo]);
            acc[oo] = fmaf(xgv.y, w4.y, acc[oo]);
            acc[oo] = fmaf(xgv.z, w4.z, acc[oo]);
            acc[oo] = fmaf(xgv.w, w4.w, acc[oo]);
        }
    }
#pragma unroll
    for (int oo = 0; oo < 6; oo++) {
#pragma unroll
        for (int off = 16; off; off >>= 1)
            acc[oo] += __shfl_down_sync(0xffffffffu, acc[oo], off);
    }
    if (lane == 0) {
        float* dst = abc + (size_t)row * 48;
#pragma unroll
        for (int oo = 0; oo < 6; oo++) {
            const int o = obase + oo;
            float v = acc[oo];
            if (o < 16) {
                float dlt = softplus_fast(v);
                dst[o] = __expf(dlt * Adiag[o]);    // A_bar
            } else {
                dst[o] = v;                          // Bt (16..31) / Ct (32..47)
            }
        }
    }
}

// ---------------------------------------------------------------------------
// Kernel 3: sequential scan over T, one block per batch.
// warp 0 = consumer (16 chains), warps 1..3 = producers (double-buffered SMEM).
// Emits s = Ct*h per token and h_final.
// ---------------------------------------------------------------------------
#define CH 128
#define NCH (TT / CH)

__global__ void __launch_bounds__(128)
k_scan(const float* __restrict__ abc, const float* __restrict__ mask,
       const float* __restrict__ h0, float* __restrict__ sout,
       float* __restrict__ out, int out_size)
{
    __shared__ float sbuf[2][CH * 48];
    __shared__ float smask[2][CH];

    const int b    = blockIdx.x;
    const int tid  = threadIdx.x;
    const int lane = tid & 31;
    const int warp = tid >> 5;

    const float* abc_b  = abc  + (size_t)b * TT * 48;
    const float* mask_b = mask + (size_t)b * TT;

    // preload chunk 0 with all 128 threads
    {
        const float4* src = (const float4*)abc_b;
        float4* dst = (float4*)sbuf[0];
        for (int i = tid; i < CH * 48 / 4; i += 128) dst[i] = src[i];
        const float4* ms = (const float4*)mask_b;
        float4* md = (float4*)smask[0];
        for (int i = tid; i < CH / 4; i += 128) md[i] = ms[i];
    }
    __syncthreads();

    float h = 0.0f;
    if (warp == 0 && lane < DS) h = h0[b * DS + lane];

    for (int c = 0; c < NCH; c++) {
        const int cur = c & 1;
        if (warp > 0 && c + 1 < NCH) {
            const int tix = tid - 32;             // 0..95
            const float4* src = (const float4*)(abc_b + (size_t)(c + 1) * CH * 48);
            float4* dst = (float4*)sbuf[cur ^ 1];
            for (int i = tix; i < CH * 48 / 4; i += 96) dst[i] = src[i];
            const float4* ms = (const float4*)(mask_b + (size_t)(c + 1) * CH);
            float4* md = (float4*)smask[cur ^ 1];
            for (int i = tix; i < CH / 4; i += 96) md[i] = ms[i];
        }
        if (warp == 0 && lane < DS) {
            const float* buf = sbuf[cur];
            float* sdst = sout + ((size_t)b * TT + (size_t)c * CH) * DS + lane;
#pragma unroll 4
            for (int t = 0; t < CH; t++) {
                const float a  = buf[t * 48 + lane];
                const float bb = buf[t * 48 + 16 + lane];
                const float ct = buf[t * 48 + 32 + lane];
                const float m  = smask[cur][t];
                const float im = 1.0f - m;
                const float hc = tanh_fast(fmaf(a, h, bb));
                h = fmaf(m, hc, im * h);           // m*hc + (1-m)*h
                sdst[(size_t)t * DS] = ct * h;
            }
        }
        __syncthreads();
    }

    if (warp == 0 && lane < DS && out_size >= MM * DM + BB * DS)
        out[(size_t)MM * DM + b * DS + lane] = h;
}

// ---------------------------------------------------------------------------
// Kernel 4: y = D*x + s @ W_out^T.  One block (256 threads) per token; each
// thread produces one float4 of y.
// ---------------------------------------------------------------------------
__global__ void __launch_bounds__(256)
k_out(const float* __restrict__ sv_g, const float* __restrict__ x,
      const float* __restrict__ Wout, const float* __restrict__ Dv,
      float* __restrict__ y)
{
    __shared__ float sv[DS];
    const int row = blockIdx.x;
    const int tid = threadIdx.x;

    if (tid < DS) sv[tid] = sv_g[(size_t)row * DS + tid];
    __syncthreads();

    const int d = tid * 4;
    const size_t base = (size_t)row * DM + d;
    float4 xv = *(const float4*)(x + base);
    float4 dd = *(const float4*)(Dv + d);

    float ys[4] = {0.f, 0.f, 0.f, 0.f};
#pragma unroll
    for (int r = 0; r < 4; r++) {
        const float* wrow = Wout + (size_t)(d + r) * DS;
#pragma unroll
        for (int s4 = 0; s4 < DS; s4 += 4) {
            float4 w4 = *(const float4*)(wrow + s4);
            ys[r] = fmaf(sv[s4 + 0], w4.x, ys[r]);
            ys[r] = fmaf(sv[s4 + 1], w4.y, ys[r]);
            ys[r] = fmaf(sv[s4 + 2], w4.z, ys[r]);
            ys[r] = fmaf(sv[s4 + 3], w4.w, ys[r]);
        }
    }
    float4 out4 = make_float4(ys[0] + dd.x * xv.x, ys[1] + dd.y * xv.y,
                              ys[2] + dd.z * xv.z, ys[3] + dd.w * xv.w);
    *(float4*)(y + base) = out4;
}

// ---------------------------------------------------------------------------
extern "C" void kernel_launch(void* const* d_in, const int* in_sizes, int n_in,
                              void* d_out, int out_size)
{
    const float* x      = (const float*)d_in[0];
    const float* h0     = (const float*)d_in[1];
    const float* mask   = (const float*)d_in[2];
    const float* A_diag = (const float*)d_in[3];
    const float* W_del  = (const float*)d_in[4];
    const float* W_B    = (const float*)d_in[5];
    const float* W_C    = (const float*)d_in[6];
    const float* W_out  = (const float*)d_in[7];
    const float* Dv     = (const float*)d_in[8];
    const float* W_gate = (const float*)d_in[9];
    const float* b_gate = (const float*)d_in[10];
    const float* ln_w   = (const float*)d_in[11];
    const float* ln_b   = (const float*)d_in[12];
    float* out = (float*)d_out;

    float* gp;  cudaGetSymbolAddress((void**)&gp,  g_gatepre);
    float* abc; cudaGetSymbolAddress((void**)&abc, g_abc);
    float* sg;  cudaGetSymbolAddress((void**)&sg,  g_s);

    dim3 g1(MM / BM, DM / BN);
    k_gate_gemm<<<g1, 256>>>(x, W_gate, b_gate, gp);

    k_ln_proj<<<MM, 256>>>(gp, x, ln_w, ln_b, W_del, W_B, W_C, A_diag, abc);

    k_scan<<<BB, 128>>>(abc, mask, h0, sg, out, out_size);

    k_out<<<MM, 256>>>(sg, x, W_out, Dv, out);
}

// round 6
// speedup vs baseline: 3.2561x; 3.2558x over previous
#include <cuda_runtime.h>
#include <cuda_fp16.h>
#include <cstdint>

#define BB     8
#define TT     4096
#define DM     1024
#define DS     16
#define MM     (BB * TT)
#define LN_EPS 1e-5f

// ------------------------- scratch (static, no alloc) ----------------------
__device__ float   g_gatepre[(size_t)MM * DM];   // 128 MB
__device__ __half  g_xb  [(size_t)MM * DM];      // x fp16
__device__ __half  g_xgb [(size_t)MM * DM];      // xg fp16
__device__ __half  g_wb  [DM * DM];              // W_gate fp16
__device__ __half  g_wall[128 * DM];             // Wd|Wb|Wc|pad fp16
__device__ float   g_abc [(size_t)MM * 48];      // A_bar|Bt|Ct
__device__ float   g_s   [(size_t)MM * DS];      // Ct*h

// ----------------------------- helpers -------------------------------------
__device__ __forceinline__ uint32_t smem_u32(const void* p) {
    uint32_t a;
    asm("{ .reg .u64 t; cvta.to.shared.u64 t, %1; cvt.u32.u64 %0, t; }"
        : "=r"(a) : "l"(p));
    return a;
}
__device__ __forceinline__ void cp16(uint32_t dst, const void* src) {
    asm volatile("cp.async.cg.shared.global [%0], [%1], 16;" :: "r"(dst), "l"(src));
}
#define CP_COMMIT() asm volatile("cp.async.commit_group;" ::: "memory")
#define CP_WAIT(n)  asm volatile("cp.async.wait_group %0;" :: "n"(n) : "memory")
#define SWZ(o) ((o) ^ (((o) >> 3) & 0x70))

#define LDSM_X4(r, a) \
    asm volatile("ldmatrix.sync.aligned.m8n8.x4.shared.b16 {%0,%1,%2,%3}, [%4];" \
        : "=r"((r)[0]), "=r"((r)[1]), "=r"((r)[2]), "=r"((r)[3]) : "r"(a))

__device__ __forceinline__ void mma16816(float* c, const uint32_t* a,
                                         uint32_t b0, uint32_t b1) {
    asm volatile(
        "mma.sync.aligned.m16n8k16.row.col.f32.f16.f16.f32 "
        "{%0,%1,%2,%3}, {%4,%5,%6,%7}, {%8,%9}, {%0,%1,%2,%3};"
        : "+f"(c[0]), "+f"(c[1]), "+f"(c[2]), "+f"(c[3])
        : "r"(a[0]), "r"(a[1]), "r"(a[2]), "r"(a[3]), "r"(b0), "r"(b1));
}

__device__ __forceinline__ float tanh_fast(float x) {
    float r; asm("tanh.approx.f32 %0, %1;" : "=f"(r) : "f"(x)); return r;
}
__device__ __forceinline__ float sigmoid_fast(float x) {
    return 1.0f / (1.0f + __expf(-x));
}
__device__ __forceinline__ float softplus_fast(float x) {
    if (x > 20.0f) return x;
    return __logf(1.0f + __expf(x));
}

// ---------------------------------------------------------------------------
// conversions (fp32 -> fp16)
// ---------------------------------------------------------------------------
__global__ void __launch_bounds__(256)
k_convx(const float4* __restrict__ xin, __half2* __restrict__ xb)
{
    const int n4 = MM * DM / 4;
    for (int i = blockIdx.x * 256 + threadIdx.x; i < n4; i += gridDim.x * 256) {
        float4 v = xin[i];
        xb[i * 2]     = __floats2half2_rn(v.x, v.y);
        xb[i * 2 + 1] = __floats2half2_rn(v.z, v.w);
    }
}
__global__ void __launch_bounds__(256)
k_convw(const float4* __restrict__ win, __half2* __restrict__ wb)
{
    const int i = blockIdx.x * 256 + threadIdx.x;   // covers DM*DM/4 exactly
    float4 v = win[i];
    wb[i * 2]     = __floats2half2_rn(v.x, v.y);
    wb[i * 2 + 1] = __floats2half2_rn(v.z, v.w);
}
__global__ void __launch_bounds__(256)
k_convwall(const float* __restrict__ Wd, const float* __restrict__ Wb,
           const float* __restrict__ Wc, __half2* __restrict__ wall)
{
    const int i   = blockIdx.x * 256 + threadIdx.x; // 32768 float4 slots (128 rows)
    const int row = i >> 8;
    const int k4  = i & 255;
    float4 v = make_float4(0.f, 0.f, 0.f, 0.f);
    if (row < 48) {
        const float* s = (row < 16) ? (Wd + (size_t)row * DM)
                       : (row < 32) ? (Wb + (size_t)(row - 16) * DM)
                                    : (Wc + (size_t)(row - 32) * DM);
        v = *(const float4*)(s + k4 * 4);
    }
    wall[i * 2]     = __floats2half2_rn(v.x, v.y);
    wall[i * 2 + 1] = __floats2half2_rn(v.z, v.w);
}

// ---------------------------------------------------------------------------
// fp16 mma.sync GEMM:  D[m][n] = sum_k A[m][k] * B[n][k]
// CTA tile 128x128, BK=64, 3-stage cp.async, 4 warps of 64x64, HMMA m16n8k16.
// EPI 0: store fp32 tile to C (stride DM).  EPI 1: abc transform (cols 0..47).
// Grid: (n_blocks, m_blocks) — n fastest for L2-friendly A reuse.
// ---------------------------------------------------------------------------
#define STGB 32768          // (128 A rows + 128 B rows) * 128 B
#define NK   16             // 1024 / 64

template<int EPI>
__global__ void __launch_bounds__(128, 1)
k_gemm(const __half* __restrict__ A, const __half* __restrict__ Bw,
       const float* __restrict__ Adiag, float* __restrict__ C)
{
    extern __shared__ char sraw[];
    const uint32_t sb = (smem_u32(sraw) + 1023u) & ~1023u;
    const int tid = threadIdx.x, wid = tid >> 5, lane = tid & 31;
    const int wm = wid >> 1, wn = wid & 1;          // 2x2 warp grid, 64x64 each
    const int n0 = blockIdx.x * 128, m0 = blockIdx.y * 128;

    const int rr = tid >> 3, cc = tid & 7;          // stage loader indices
    const __half* ag = A  + (size_t)(m0 + rr) * DM + cc * 8;
    const __half* bg = Bw + (size_t)(n0 + rr) * DM + cc * 8;

    auto load_stage = [&](int slot, int k) {
        const uint32_t ab = sb + slot * STGB;
        const __half* a = ag + k * 64;
#pragma unroll
        for (int i = 0; i < 8; i++) {
            uint32_t off = (uint32_t)((rr + i * 16) * 128 + cc * 16);
            cp16(ab + SWZ(off), a + (size_t)i * 16 * DM);
        }
        const uint32_t bb2 = ab + 16384;
        const __half* b = bg + k * 64;
#pragma unroll
        for (int i = 0; i < 8; i++) {
            uint32_t off = (uint32_t)((rr + i * 16) * 128 + cc * 16);
            cp16(bb2 + SWZ(off), b + (size_t)i * 16 * DM);
        }
        CP_COMMIT();
    };

    load_stage(0, 0); load_stage(1, 1); load_stage(2, 2);

    float acc[4][8][4];
#pragma unroll
    for (int i = 0; i < 4; i++)
#pragma unroll
        for (int j = 0; j < 8; j++)
#pragma unroll
            for (int q = 0; q < 4; q++) acc[i][j][q] = 0.f;

    // per-lane ldmatrix address components (within tile, before swizzle)
    const int a_row = wm * 64 + ((lane >> 3) & 1) * 8 + (lane & 7);
    const int a_cb  = (lane >> 4) << 4;                 // 0 / 16 bytes
    const int b_row = wn * 64 + ((lane >> 4) << 3) + (lane & 7);
    const int b_cb  = ((lane >> 3) & 1) << 4;           // 0 / 16 bytes

    for (int k = 0; k < NK; k++) {
        const int cur = k % 3;
        if (k <= NK - 3) CP_WAIT(2); else if (k == NK - 2) CP_WAIT(1); else CP_WAIT(0);
        __syncthreads();

        const uint32_t ab  = sb + cur * STGB;
        const uint32_t bb2 = ab + 16384;
#pragma unroll
        for (int kk = 0; kk < 4; kk++) {
            const int kb = kk * 32;                     // 16 fp16 = 32 bytes
            uint32_t af[4][4], bf[4][4];
#pragma unroll
            for (int mi = 0; mi < 4; mi++) {
                uint32_t off = (uint32_t)((a_row + mi * 16) * 128 + kb + a_cb);
                LDSM_X4(af[mi], ab + SWZ(off));
            }
#pragma unroll
            for (int nj = 0; nj < 4; nj++) {
                uint32_t off = (uint32_t)((b_row + nj * 16) * 128 + kb + b_cb);
                LDSM_X4(bf[nj], bb2 + SWZ(off));
            }
#pragma unroll
            for (int mi = 0; mi < 4; mi++)
#pragma unroll
                for (int nj = 0; nj < 4; nj++) {
                    mma16816(acc[mi][2 * nj],     af[mi], bf[nj][0], bf[nj][1]);
                    mma16816(acc[mi][2 * nj + 1], af[mi], bf[nj][2], bf[nj][3]);
                }
        }
        __syncthreads();
        if (k + 3 < NK) load_stage(cur, k + 3);
    }

    // ------------------------------- epilogue -------------------------------
    const int g = lane >> 2, t2 = (lane & 3) * 2;
    if (EPI == 0) {
#pragma unroll
        for (int mi = 0; mi < 4; mi++) {
            const int row = m0 + wm * 64 + mi * 16 + g;
#pragma unroll
            for (int ni = 0; ni < 8; ni++) {
                const int col = n0 + wn * 64 + ni * 8 + t2;
                float* p0 = C + (size_t)row * DM + col;
                float* p1 = C + (size_t)(row + 8) * DM + col;
                asm volatile("st.global.v2.f32 [%0], {%1,%2};"
                             :: "l"(p0), "f"(acc[mi][ni][0]), "f"(acc[mi][ni][1]));
                asm volatile("st.global.v2.f32 [%0], {%1,%2};"
                             :: "l"(p1), "f"(acc[mi][ni][2]), "f"(acc[mi][ni][3]));
            }
        }
    } else {
        if (wn == 0) {                                   // cols 0..63; keep <48
#pragma unroll
            for (int mi = 0; mi < 4; mi++) {
                const int row = m0 + wm * 64 + mi * 16 + g;
#pragma unroll
                for (int ni = 0; ni < 6; ni++) {         // cols 0..47
                    const int col = ni * 8 + t2;
                    float v0 = acc[mi][ni][0], v1 = acc[mi][ni][1];
                    float v2 = acc[mi][ni][2], v3 = acc[mi][ni][3];
                    if (col < 16) {
                        const float a0 = __ldg(Adiag + col), a1 = __ldg(Adiag + col + 1);
                        v0 = __expf(softplus_fast(v0) * a0);
                        v1 = __expf(softplus_fast(v1) * a1);
                        v2 = __expf(softplus_fast(v2) * a0);
                        v3 = __expf(softplus_fast(v3) * a1);
                    }
                    float* p0 = C + (size_t)row * 48 + col;
                    float* p1 = C + (size_t)(row + 8) * 48 + col;
                    p0[0] = v0; p0[1] = v1;
                    p1[0] = v2; p1[1] = v3;
                }
            }
        }
    }
}

// ---------------------------------------------------------------------------
// LN(+bias) + sigmoid gate, xg = gate*x (fp16). Warp per token, 8 tokens/warp.
// ---------------------------------------------------------------------------
__global__ void __launch_bounds__(256)
k_lnxg(const float* __restrict__ gp, const float* __restrict__ x,
       const float* __restrict__ bg, const float* __restrict__ lnw,
       const float* __restrict__ lnb, __half2* __restrict__ xgb)
{
    const int lane = threadIdx.x & 31;
    const int gw = (blockIdx.x * 256 + threadIdx.x) >> 5;   // 0..4095
    for (int j = 0; j < 8; j++) {
        const int t = gw + j * 4096;
        const size_t base = (size_t)t * DM;
        float4 g[8];
        float s1 = 0.f, s2 = 0.f;
#pragma unroll
        for (int i = 0; i < 8; i++) {
            const int f = i * 32 + lane;
            float4 v = *(const float4*)(gp + base + (size_t)f * 4);
            float4 b = *(const float4*)(bg + f * 4);
            v.x += b.x; v.y += b.y; v.z += b.z; v.w += b.w;
            g[i] = v;
            s1 += v.x + v.y + v.z + v.w;
            s2 += v.x*v.x + v.y*v.y + v.z*v.z + v.w*v.w;
        }
#pragma unroll
        for (int off = 16; off; off >>= 1) {
            s1 += __shfl_xor_sync(0xffffffffu, s1, off);
            s2 += __shfl_xor_sync(0xffffffffu, s2, off);
        }
        const float mean = s1 * (1.0f / DM);
        const float rstd = rsqrtf(s2 * (1.0f / DM) - mean * mean + LN_EPS);
#pragma unroll
        for (int i = 0; i < 8; i++) {
            const int f = i * 32 + lane;
            float4 w = *(const float4*)(lnw + f * 4);
            float4 b = *(const float4*)(lnb + f * 4);
            float4 xv = *(const float4*)(x + base + (size_t)f * 4);
            float4 v = g[i];
            float4 xg;
            xg.x = xv.x * sigmoid_fast((v.x - mean) * rstd * w.x + b.x);
            xg.y = xv.y * sigmoid_fast((v.y - mean) * rstd * w.y + b.y);
            xg.z = xv.z * sigmoid_fast((v.z - mean) * rstd * w.z + b.z);
            xg.w = xv.w * sigmoid_fast((v.w - mean) * rstd * w.w + b.w);
            xgb[(base >> 1) + f * 2]     = __floats2half2_rn(xg.x, xg.y);
            xgb[(base >> 1) + f * 2 + 1] = __floats2half2_rn(xg.z, xg.w);
        }
    }
}

// ---------------------------------------------------------------------------
// scan: one block/batch, warp0 consumes, warps1-3 prefetch (double buffer)
// ---------------------------------------------------------------------------
#define CH 128
#define NCH (TT / CH)
__global__ void __launch_bounds__(128)
k_scan(const float* __restrict__ abc, const float* __restrict__ mask,
       const float* __restrict__ h0, float* __restrict__ sout,
       float* __restrict__ out, int out_size)
{
    __shared__ float sbuf[2][CH * 48];
    __shared__ float smask[2][CH];
    const int b = blockIdx.x, tid = threadIdx.x;
    const int lane = tid & 31, warp = tid >> 5;
    const float* abc_b  = abc  + (size_t)b * TT * 48;
    const float* mask_b = mask + (size_t)b * TT;
    {
        const float4* src = (const float4*)abc_b;
        float4* dst = (float4*)sbuf[0];
        for (int i = tid; i < CH * 48 / 4; i += 128) dst[i] = src[i];
        const float4* ms = (const float4*)mask_b;
        float4* md = (float4*)smask[0];
        for (int i = tid; i < CH / 4; i += 128) md[i] = ms[i];
    }
    __syncthreads();
    float h = 0.0f;
    if (warp == 0 && lane < DS) h = h0[b * DS + lane];
    for (int c = 0; c < NCH; c++) {
        const int cur = c & 1;
        if (warp > 0 && c + 1 < NCH) {
            const int tix = tid - 32;
            const float4* src = (const float4*)(abc_b + (size_t)(c + 1) * CH * 48);
            float4* dst = (float4*)sbuf[cur ^ 1];
            for (int i = tix; i < CH * 48 / 4; i += 96) dst[i] = src[i];
            const float4* ms = (const float4*)(mask_b + (size_t)(c + 1) * CH);
            float4* md = (float4*)smask[cur ^ 1];
            for (int i = tix; i < CH / 4; i += 96) md[i] = ms[i];
        }
        if (warp == 0 && lane < DS) {
            const float* buf = sbuf[cur];
            float* sdst = sout + ((size_t)b * TT + (size_t)c * CH) * DS + lane;
#pragma unroll 4
            for (int t = 0; t < CH; t++) {
                const float a  = buf[t * 48 + lane];
                const float bb = buf[t * 48 + 16 + lane];
                const float ct = buf[t * 48 + 32 + lane];
                const float m  = smask[cur][t];
                const float hc = tanh_fast(fmaf(a, h, bb));
                h = fmaf(m, hc, (1.0f - m) * h);
                sdst[(size_t)t * DS] = ct * h;
            }
        }
        __syncthreads();
    }
    if (warp == 0 && lane < DS && out_size >= MM * DM + BB * DS)
        out[(size_t)MM * DM + b * DS + lane] = h;
}

// ---------------------------------------------------------------------------
// y = D*x + s @ W_out^T. Thread t owns features 4t..4t+3 (W_out in regs),
// block processes 16 tokens.
// ---------------------------------------------------------------------------
__global__ void __launch_bounds__(256)
k_out(const float* __restrict__ sg, const float* __restrict__ x,
      const float* __restrict__ Wout, const float* __restrict__ Dv,
      float* __restrict__ y)
{
    const int t = threadIdx.x;
    const int d = t * 4;
    float4 wr[4][4];
#pragma unroll
    for (int r = 0; r < 4; r++)
#pragma unroll
        for (int q = 0; q < 4; q++)
            wr[r][q] = *(const float4*)(Wout + (size_t)(d + r) * DS + q * 4);
    const float4 dd = *(const float4*)(Dv + d);

    const int row0 = blockIdx.x * 16;
    for (int j = 0; j < 16; j++) {
        const int row = row0 + j;
        const float4 s0 = *(const float4*)(sg + (size_t)row * DS);
        const float4 s1 = *(const float4*)(sg + (size_t)row * DS + 4);
        const float4 s2 = *(const float4*)(sg + (size_t)row * DS + 8);
        const float4 s3 = *(const float4*)(sg + (size_t)row * DS + 12);
        float ys[4];
#pragma unroll
        for (int r = 0; r < 4; r++) {
            float a;
            a  = s0.x * wr[r][0].x + s0.y * wr[r][0].y + s0.z * wr[r][0].z + s0.w * wr[r][0].w;
            a += s1.x * wr[r][1].x + s1.y * wr[r][1].y + s1.z * wr[r][1].z + s1.w * wr[r][1].w;
            a += s2.x * wr[r][2].x + s2.y * wr[r][2].y + s2.z * wr[r][2].z + s2.w * wr[r][2].w;
            a += s3.x * wr[r][3].x + s3.y * wr[r][3].y + s3.z * wr[r][3].z + s3.w * wr[r][3].w;
            ys[r] = a;
        }
        const size_t base = (size_t)row * DM + d;
        const float4 xv = *(const float4*)(x + base);
        *(float4*)(y + base) = make_float4(ys[0] + dd.x * xv.x, ys[1] + dd.y * xv.y,
                                           ys[2] + dd.z * xv.z, ys[3] + dd.w * xv.w);
    }
}

// ---------------------------------------------------------------------------
extern "C" void kernel_launch(void* const* d_in, const int* in_sizes, int n_in,
                              void* d_out, int out_size)
{
    const float* x      = (const float*)d_in[0];
    const float* h0     = (const float*)d_in[1];
    const float* mask   = (const float*)d_in[2];
    const float* A_diag = (const float*)d_in[3];
    const float* W_del  = (const float*)d_in[4];
    const float* W_B    = (const float*)d_in[5];
    const float* W_C    = (const float*)d_in[6];
    const float* W_out  = (const float*)d_in[7];
    const float* Dv     = (const float*)d_in[8];
    const float* W_gate = (const float*)d_in[9];
    const float* b_gate = (const float*)d_in[10];
    const float* ln_w   = (const float*)d_in[11];
    const float* ln_b   = (const float*)d_in[12];
    float* out = (float*)d_out;

    float *gp, *abc, *sg;
    __half *xb, *xgb, *wb, *wall;
    cudaGetSymbolAddress((void**)&gp,   g_gatepre);
    cudaGetSymbolAddress((void**)&abc,  g_abc);
    cudaGetSymbolAddress((void**)&sg,   g_s);
    cudaGetSymbolAddress((void**)&xb,   g_xb);
    cudaGetSymbolAddress((void**)&xgb,  g_xgb);
    cudaGetSymbolAddress((void**)&wb,   g_wb);
    cudaGetSymbolAddress((void**)&wall, g_wall);

    const int smem_sz = 3 * STGB + 1024;    // 99328
    cudaFuncSetAttribute(k_gemm<0>, cudaFuncAttributeMaxDynamicSharedMemorySize, smem_sz);
    cudaFuncSetAttribute(k_gemm<1>, cudaFuncAttributeMaxDynamicSharedMemorySize, smem_sz);

    k_convx<<<4096, 256>>>((const float4*)x, (__half2*)xb);
    k_convw<<<1024, 256>>>((const float4*)W_gate, (__half2*)wb);
    k_convwall<<<128, 256>>>(W_del, W_B, W_C, (__half2*)wall);

    dim3 gg(DM / 128, MM / 128);            // n fastest -> A-band L2 reuse
    k_gemm<0><<<gg, 128, smem_sz>>>(xb, wb, nullptr, gp);

    k_lnxg<<<512, 256>>>(gp, x, b_gate, ln_w, ln_b, (__half2*)xgb);

    dim3 ga(1, MM / 128);
    k_gemm<1><<<ga, 128, smem_sz>>>(xgb, wall, A_diag, abc);

    k_scan<<<BB, 128>>>(abc, mask, h0, sg, out, out_size);

    k_out<<<MM / 16, 256>>>(sg, x, W_out, Dv, out);
}

// round 7
// speedup vs baseline: 4.2860x; 1.3163x over previous
#include <cuda_runtime.h>
#include <cuda_fp16.h>
#include <cstdint>

#define BB     8
#define TT     4096
#define DM     1024
#define DS     16
#define MM     (BB * TT)
#define LN_EPS 1e-5f

// ------------------------- scratch (static, no alloc) ----------------------
__device__ __half  g_gph [(size_t)MM * DM];      // gate_pre fp16 (64 MB)
__device__ __half  g_xb  [(size_t)MM * DM];      // x fp16
__device__ __half  g_xgb [(size_t)MM * DM];      // xg fp16
__device__ __half  g_wb  [DM * DM];              // W_gate fp16
__device__ __half  g_wall[128 * DM];             // Wd|Wb|Wc|pad fp16
__device__ float   g_abc [(size_t)MM * 48];      // A_bar|Bt|Ct
__device__ float   g_s   [(size_t)MM * DS];      // Ct*h

// ----------------------------- helpers -------------------------------------
__device__ __forceinline__ uint32_t smem_u32(const void* p) {
    uint32_t a;
    asm("{ .reg .u64 t; cvta.to.shared.u64 t, %1; cvt.u32.u64 %0, t; }"
        : "=r"(a) : "l"(p));
    return a;
}
__device__ __forceinline__ void cp16(uint32_t dst, const void* src) {
    asm volatile("cp.async.cg.shared.global [%0], [%1], 16;" :: "r"(dst), "l"(src));
}
#define CP_COMMIT() asm volatile("cp.async.commit_group;" ::: "memory")
#define CP_WAIT(n)  asm volatile("cp.async.wait_group %0;" :: "n"(n) : "memory")
#define SWZ(o) ((o) ^ (((o) >> 3) & 0x70))

#define LDSM_X4(r, a) \
    asm volatile("ldmatrix.sync.aligned.m8n8.x4.shared.b16 {%0,%1,%2,%3}, [%4];" \
        : "=r"((r)[0]), "=r"((r)[1]), "=r"((r)[2]), "=r"((r)[3]) : "r"(a))

__device__ __forceinline__ void mma16816(float* c, const uint32_t* a,
                                         uint32_t b0, uint32_t b1) {
    asm volatile(
        "mma.sync.aligned.m16n8k16.row.col.f32.f16.f16.f32 "
        "{%0,%1,%2,%3}, {%4,%5,%6,%7}, {%8,%9}, {%0,%1,%2,%3};"
        : "+f"(c[0]), "+f"(c[1]), "+f"(c[2]), "+f"(c[3])
        : "r"(a[0]), "r"(a[1]), "r"(a[2]), "r"(a[3]), "r"(b0), "r"(b1));
}

__device__ __forceinline__ float tanh_fast(float x) {
    float r; asm("tanh.approx.f32 %0, %1;" : "=f"(r) : "f"(x)); return r;
}
__device__ __forceinline__ float sigmoid_fast(float x) {
    return 1.0f / (1.0f + __expf(-x));
}
__device__ __forceinline__ float softplus_fast(float x) {
    if (x > 20.0f) return x;
    return __logf(1.0f + __expf(x));
}

// ---------------------------------------------------------------------------
// conversions (fp32 -> fp16)
// ---------------------------------------------------------------------------
__global__ void __launch_bounds__(256)
k_convx(const float4* __restrict__ xin, __half2* __restrict__ xb)
{
    const int n4 = MM * DM / 4;
    for (int i = blockIdx.x * 256 + threadIdx.x; i < n4; i += gridDim.x * 256) {
        float4 v = xin[i];
        xb[i * 2]     = __floats2half2_rn(v.x, v.y);
        xb[i * 2 + 1] = __floats2half2_rn(v.z, v.w);
    }
}
__global__ void __launch_bounds__(256)
k_convw(const float4* __restrict__ win, __half2* __restrict__ wb)
{
    const int i = blockIdx.x * 256 + threadIdx.x;   // covers DM*DM/4 exactly
    float4 v = win[i];
    wb[i * 2]     = __floats2half2_rn(v.x, v.y);
    wb[i * 2 + 1] = __floats2half2_rn(v.z, v.w);
}
__global__ void __launch_bounds__(256)
k_convwall(const float* __restrict__ Wd, const float* __restrict__ Wb,
           const float* __restrict__ Wc, __half2* __restrict__ wall)
{
    const int i   = blockIdx.x * 256 + threadIdx.x; // 32768 float4 slots (128 rows)
    const int row = i >> 8;
    const int k4  = i & 255;
    float4 v = make_float4(0.f, 0.f, 0.f, 0.f);
    if (row < 48) {
        const float* s = (row < 16) ? (Wd + (size_t)row * DM)
                       : (row < 32) ? (Wb + (size_t)(row - 16) * DM)
                                    : (Wc + (size_t)(row - 32) * DM);
        v = *(const float4*)(s + k4 * 4);
    }
    wall[i * 2]     = __floats2half2_rn(v.x, v.y);
    wall[i * 2 + 1] = __floats2half2_rn(v.z, v.w);
}

// ---------------------------------------------------------------------------
// fp16 mma.sync GEMM:  D[m][n] = sum_k A[m][k] * B[n][k]
// CTA tile 128x128, BK=64, 3-stage cp.async, 8 warps (2x4 grid, 64x32 tiles).
// EPI 0: store fp16 tile to Ch (stride DM).  EPI 1: abc transform (cols<48).
// ---------------------------------------------------------------------------
#define STGB 32768
#define NK   16

template<int EPI>
__global__ void __launch_bounds__(256, 1)
k_gemm(const __half* __restrict__ A, const __half* __restrict__ Bw,
       const float* __restrict__ Adiag, __half* __restrict__ Ch,
       float* __restrict__ Cf)
{
    extern __shared__ char sraw[];
    const uint32_t sb = (smem_u32(sraw) + 1023u) & ~1023u;
    const int tid = threadIdx.x, wid = tid >> 5, lane = tid & 31;
    const int wm = wid >> 2, wn = wid & 3;          // 2x4 warp grid, 64x32 each
    const int n0 = blockIdx.x * 128, m0 = blockIdx.y * 128;

    const int rr = tid >> 3, cc = tid & 7;          // 32 rows / pass
    const __half* ag = A  + (size_t)(m0 + rr) * DM + cc * 8;
    const __half* bg = Bw + (size_t)(n0 + rr) * DM + cc * 8;

    auto load_stage = [&](int slot, int k) {
        const uint32_t ab = sb + slot * STGB;
        const __half* a = ag + k * 64;
#pragma unroll
        for (int i = 0; i < 4; i++) {
            uint32_t off = (uint32_t)((rr + i * 32) * 128 + cc * 16);
            cp16(ab + SWZ(off), a + (size_t)i * 32 * DM);
        }
        const uint32_t bb2 = ab + 16384;
        const __half* b = bg + k * 64;
#pragma unroll
        for (int i = 0; i < 4; i++) {
            uint32_t off = (uint32_t)((rr + i * 32) * 128 + cc * 16);
            cp16(bb2 + SWZ(off), b + (size_t)i * 32 * DM);
        }
        CP_COMMIT();
    };

    load_stage(0, 0); load_stage(1, 1); load_stage(2, 2);

    float acc[4][4][4];
#pragma unroll
    for (int i = 0; i < 4; i++)
#pragma unroll
        for (int j = 0; j < 4; j++)
#pragma unroll
            for (int q = 0; q < 4; q++) acc[i][j][q] = 0.f;

    const int a_row = wm * 64 + ((lane >> 3) & 1) * 8 + (lane & 7);
    const int a_cb  = (lane >> 4) << 4;
    const int b_row = wn * 32 + ((lane >> 4) << 3) + (lane & 7);
    const int b_cb  = ((lane >> 3) & 1) << 4;

    for (int k = 0; k < NK; k++) {
        const int cur = k % 3;
        if (k <= NK - 3) CP_WAIT(2); else if (k == NK - 2) CP_WAIT(1); else CP_WAIT(0);
        __syncthreads();

        const uint32_t ab  = sb + cur * STGB;
        const uint32_t bb2 = ab + 16384;
#pragma unroll
        for (int kk = 0; kk < 4; kk++) {
            const int kb = kk * 32;
            uint32_t af[4][4], bf[2][4];
#pragma unroll
            for (int mi = 0; mi < 4; mi++) {
                uint32_t off = (uint32_t)((a_row + mi * 16) * 128 + kb + a_cb);
                LDSM_X4(af[mi], ab + SWZ(off));
            }
#pragma unroll
            for (int nj = 0; nj < 2; nj++) {
                uint32_t off = (uint32_t)((b_row + nj * 16) * 128 + kb + b_cb);
                LDSM_X4(bf[nj], bb2 + SWZ(off));
            }
#pragma unroll
            for (int mi = 0; mi < 4; mi++)
#pragma unroll
                for (int nj = 0; nj < 2; nj++) {
                    mma16816(acc[mi][2 * nj],     af[mi], bf[nj][0], bf[nj][1]);
                    mma16816(acc[mi][2 * nj + 1], af[mi], bf[nj][2], bf[nj][3]);
                }
        }
        __syncthreads();
        if (k + 3 < NK) load_stage(cur, k + 3);
    }

    // ------------------------------- epilogue -------------------------------
    const int g = lane >> 2, t2 = (lane & 3) * 2;
    if (EPI == 0) {
#pragma unroll
        for (int mi = 0; mi < 4; mi++) {
            const int row = m0 + wm * 64 + mi * 16 + g;
#pragma unroll
            for (int ni = 0; ni < 4; ni++) {
                const int col = n0 + wn * 32 + ni * 8 + t2;
                *(__half2*)(Ch + (size_t)row * DM + col) =
                    __floats2half2_rn(acc[mi][ni][0], acc[mi][ni][1]);
                *(__half2*)(Ch + (size_t)(row + 8) * DM + col) =
                    __floats2half2_rn(acc[mi][ni][2], acc[mi][ni][3]);
            }
        }
    } else {
#pragma unroll
        for (int mi = 0; mi < 4; mi++) {
            const int row = m0 + wm * 64 + mi * 16 + g;
#pragma unroll
            for (int ni = 0; ni < 4; ni++) {
                const int col = wn * 32 + ni * 8 + t2;
                if (col < 48) {
                    float v0 = acc[mi][ni][0], v1 = acc[mi][ni][1];
                    float v2 = acc[mi][ni][2], v3 = acc[mi][ni][3];
                    if (col < 16) {
                        const float a0 = __ldg(Adiag + col), a1 = __ldg(Adiag + col + 1);
                        v0 = __expf(softplus_fast(v0) * a0);
                        v1 = __expf(softplus_fast(v1) * a1);
                        v2 = __expf(softplus_fast(v2) * a0);
                        v3 = __expf(softplus_fast(v3) * a1);
                    }
                    float* p0 = Cf + (size_t)row * 48 + col;
                    float* p1 = Cf + (size_t)(row + 8) * 48 + col;
                    p0[0] = v0; p0[1] = v1;
                    p1[0] = v2; p1[1] = v3;
                }
            }
        }
    }
}

// ---------------------------------------------------------------------------
// LN(+bias) + sigmoid gate, xg = gate*x (fp16 in, fp16 out).
// Warp per token, 8 tokens/warp.
// ---------------------------------------------------------------------------
__global__ void __launch_bounds__(256)
k_lnxg(const __half* __restrict__ gph, const __half* __restrict__ xb,
       const float* __restrict__ bg, const float* __restrict__ lnw,
       const float* __restrict__ lnb, __half2* __restrict__ xgb)
{
    const int lane = threadIdx.x & 31;
    const int gw = (blockIdx.x * 256 + threadIdx.x) >> 5;   // 0..4095
    for (int j = 0; j < 8; j++) {
        const int t = gw + j * 4096;
        const size_t base = (size_t)t * DM;
        float4 g[8];
        float s1 = 0.f, s2 = 0.f;
#pragma unroll
        for (int i = 0; i < 8; i++) {
            const int f = i * 32 + lane;
            const __half2* gp2 = (const __half2*)(gph + base + f * 4);
            float2 p0 = __half22float2(gp2[0]);
            float2 p1 = __half22float2(gp2[1]);
            float4 b = *(const float4*)(bg + f * 4);
            float4 v = make_float4(p0.x + b.x, p0.y + b.y, p1.x + b.z, p1.y + b.w);
            g[i] = v;
            s1 += v.x + v.y + v.z + v.w;
            s2 += v.x*v.x + v.y*v.y + v.z*v.z + v.w*v.w;
        }
#pragma unroll
        for (int off = 16; off; off >>= 1) {
            s1 += __shfl_xor_sync(0xffffffffu, s1, off);
            s2 += __shfl_xor_sync(0xffffffffu, s2, off);
        }
        const float mean = s1 * (1.0f / DM);
        const float rstd = rsqrtf(s2 * (1.0f / DM) - mean * mean + LN_EPS);
#pragma unroll
        for (int i = 0; i < 8; i++) {
            const int f = i * 32 + lane;
            float4 w = *(const float4*)(lnw + f * 4);
            float4 b = *(const float4*)(lnb + f * 4);
            const __half2* xp2 = (const __half2*)(xb + base + f * 4);
            float2 x0 = __half22float2(xp2[0]);
            float2 x1 = __half22float2(xp2[1]);
            float4 v = g[i];
            float4 xg;
            xg.x = x0.x * sigmoid_fast((v.x - mean) * rstd * w.x + b.x);
            xg.y = x0.y * sigmoid_fast((v.y - mean) * rstd * w.y + b.y);
            xg.z = x1.x * sigmoid_fast((v.z - mean) * rstd * w.z + b.z);
            xg.w = x1.y * sigmoid_fast((v.w - mean) * rstd * w.w + b.w);
            xgb[(base >> 1) + f * 2]     = __floats2half2_rn(xg.x, xg.y);
            xgb[(base >> 1) + f * 2 + 1] = __floats2half2_rn(xg.z, xg.w);
        }
    }
}

// ---------------------------------------------------------------------------
// scan: one block/batch, warp0 consumes, warps1-3 prefetch (double buffer)
// ---------------------------------------------------------------------------
#define CH 128
#define NCH (TT / CH)
__global__ void __launch_bounds__(128)
k_scan(const float* __restrict__ abc, const float* __restrict__ mask,
       const float* __restrict__ h0, float* __restrict__ sout,
       float* __restrict__ out, int out_size)
{
    __shared__ float sbuf[2][CH * 48];
    __shared__ float smask[2][CH];
    const int b = blockIdx.x, tid = threadIdx.x;
    const int lane = tid & 31, warp = tid >> 5;
    const float* abc_b  = abc  + (size_t)b * TT * 48;
    const float* mask_b = mask + (size_t)b * TT;
    {
        const float4* src = (const float4*)abc_b;
        float4* dst = (float4*)sbuf[0];
        for (int i = tid; i < CH * 48 / 4; i += 128) dst[i] = src[i];
        const float4* ms = (const float4*)mask_b;
        float4* md = (float4*)smask[0];
        for (int i = tid; i < CH / 4; i += 128) md[i] = ms[i];
    }
    __syncthreads();
    float h = 0.0f;
    if (warp == 0 && lane < DS) h = h0[b * DS + lane];
    for (int c = 0; c < NCH; c++) {
        const int cur = c & 1;
        if (warp > 0 && c + 1 < NCH) {
            const int tix = tid - 32;
            const float4* src = (const float4*)(abc_b + (size_t)(c + 1) * CH * 48);
            float4* dst = (float4*)sbuf[cur ^ 1];
            for (int i = tix; i < CH * 48 / 4; i += 96) dst[i] = src[i];
            const float4* ms = (const float4*)(mask_b + (size_t)(c + 1) * CH);
            float4* md = (float4*)smask[cur ^ 1];
            for (int i = tix; i < CH / 4; i += 96) md[i] = ms[i];
        }
        if (warp == 0 && lane < DS) {
            const float* buf = sbuf[cur];
            float* sdst = sout + ((size_t)b * TT + (size_t)c * CH) * DS + lane;
#pragma unroll 4
            for (int t = 0; t < CH; t++) {
                const float a  = buf[t * 48 + lane];
                const float bb = buf[t * 48 + 16 + lane];
                const float ct = buf[t * 48 + 32 + lane];
                const float m  = smask[cur][t];
                const float hc = tanh_fast(fmaf(a, h, bb));
                h = fmaf(m, hc, (1.0f - m) * h);
                sdst[(size_t)t * DS] = ct * h;
            }
        }
        __syncthreads();
    }
    if (warp == 0 && lane < DS && out_size >= MM * DM + BB * DS)
        out[(size_t)MM * DM + b * DS + lane] = h;
}

// ---------------------------------------------------------------------------
// y = D*x + s @ W_out^T. Thread t owns features 4t..4t+3 (W_out in regs),
// block processes 16 tokens.
// ---------------------------------------------------------------------------
__global__ void __launch_bounds__(256)
k_out(const float* __restrict__ sg, const float* __restrict__ x,
      const float* __restrict__ Wout, const float* __restrict__ Dv,
      float* __restrict__ y)
{
    const int t = threadIdx.x;
    const int d = t * 4;
    float4 wr[4][4];
#pragma unroll
    for (int r = 0; r < 4; r++)
#pragma unroll
        for (int q = 0; q < 4; q++)
            wr[r][q] = *(const float4*)(Wout + (size_t)(d + r) * DS + q * 4);
    const float4 dd = *(const float4*)(Dv + d);

    const int row0 = blockIdx.x * 16;
    for (int j = 0; j < 16; j++) {
        const int row = row0 + j;
        const float4 s0 = *(const float4*)(sg + (size_t)row * DS);
        const float4 s1 = *(const float4*)(sg + (size_t)row * DS + 4);
        const float4 s2 = *(const float4*)(sg + (size_t)row * DS + 8);
        const float4 s3 = *(const float4*)(sg + (size_t)row * DS + 12);
        float ys[4];
#pragma unroll
        for (int r = 0; r < 4; r++) {
            float a;
            a  = s0.x * wr[r][0].x + s0.y * wr[r][0].y + s0.z * wr[r][0].z + s0.w * wr[r][0].w;
            a += s1.x * wr[r][1].x + s1.y * wr[r][1].y + s1.z * wr[r][1].z + s1.w * wr[r][1].w;
            a += s2.x * wr[r][2].x + s2.y * wr[r][2].y + s2.z * wr[r][2].z + s2.w * wr[r][2].w;
            a += s3.x * wr[r][3].x + s3.y * wr[r][3].y + s3.z * wr[r][3].z + s3.w * wr[r][3].w;
            ys[r] = a;
        }
        const size_t base = (size_t)row * DM + d;
        const float4 xv = *(const float4*)(x + base);
        *(float4*)(y + base) = make_float4(ys[0] + dd.x * xv.x, ys[1] + dd.y * xv.y,
                                           ys[2] + dd.z * xv.z, ys[3] + dd.w * xv.w);
    }
}

// ---------------------------------------------------------------------------
extern "C" void kernel_launch(void* const* d_in, const int* in_sizes, int n_in,
                              void* d_out, int out_size)
{
    const float* x      = (const float*)d_in[0];
    const float* h0     = (const float*)d_in[1];
    const float* mask   = (const float*)d_in[2];
    const float* A_diag = (const float*)d_in[3];
    const float* W_del  = (const float*)d_in[4];
    const float* W_B    = (const float*)d_in[5];
    const float* W_C    = (const float*)d_in[6];
    const float* W_out  = (const float*)d_in[7];
    const float* Dv     = (const float*)d_in[8];
    const float* W_gate = (const float*)d_in[9];
    const float* b_gate = (const float*)d_in[10];
    const float* ln_w   = (const float*)d_in[11];
    const float* ln_b   = (const float*)d_in[12];
    float* out = (float*)d_out;

    float *abc, *sg;
    __half *gph, *xb, *xgb, *wb, *wall;
    cudaGetSymbolAddress((void**)&gph,  g_gph);
    cudaGetSymbolAddress((void**)&abc,  g_abc);
    cudaGetSymbolAddress((void**)&sg,   g_s);
    cudaGetSymbolAddress((void**)&xb,   g_xb);
    cudaGetSymbolAddress((void**)&xgb,  g_xgb);
    cudaGetSymbolAddress((void**)&wb,   g_wb);
    cudaGetSymbolAddress((void**)&wall, g_wall);

    const int smem_sz = 3 * STGB + 1024;    // 99328
    cudaFuncSetAttribute(k_gemm<0>, cudaFuncAttributeMaxDynamicSharedMemorySize, smem_sz);
    cudaFuncSetAttribute(k_gemm<1>, cudaFuncAttributeMaxDynamicSharedMemorySize, smem_sz);

    k_convx<<<4096, 256>>>((const float4*)x, (__half2*)xb);
    k_convw<<<1024, 256>>>((const float4*)W_gate, (__half2*)wb);
    k_convwall<<<128, 256>>>(W_del, W_B, W_C, (__half2*)wall);

    dim3 gg(DM / 128, MM / 128);            // n fastest -> A-band L2 reuse
    k_gemm<0><<<gg, 256, smem_sz>>>(xb, wb, nullptr, gph, nullptr);

    k_lnxg<<<512, 256>>>(gph, xb, b_gate, ln_w, ln_b, (__half2*)xgb);

    dim3 ga(1, MM / 128);
    k_gemm<1><<<ga, 256, smem_sz>>>(xgb, wall, A_diag, nullptr, abc);

    k_scan<<<BB, 128>>>(abc, mask, h0, sg, out, out_size);

    k_out<<<MM / 16, 256>>>(sg, x, W_out, Dv, out);
}

// round 9
// speedup vs baseline: 4.6267x; 1.0795x over previous
#include <cuda_runtime.h>
#include <cuda_fp16.h>
#include <cstdint>

#define BB     8
#define TT     4096
#define DM     1024
#define DS     16
#define MM     (BB * TT)
#define LN_EPS 1e-5f

// ------------------------- scratch (static, no alloc) ----------------------
__device__ __half  g_gph [(size_t)MM * DM];      // gate_pre fp16 (64 MB)
__device__ __half  g_xb  [(size_t)MM * DM];      // x fp16
__device__ __half  g_xgb [(size_t)MM * DM];      // xg fp16
__device__ __half  g_wb  [DM * DM];              // W_gate fp16
__device__ __half  g_wall[128 * DM];             // Wd|Wb|Wc|pad fp16
__device__ float   g_abc [(size_t)MM * 48];      // A_bar|Bt|Ct
__device__ float   g_s   [(size_t)MM * DS];      // Ct*h

// ----------------------------- helpers -------------------------------------
__device__ __forceinline__ uint32_t smem_u32(const void* p) {
    uint32_t a;
    asm("{ .reg .u64 t; cvta.to.shared.u64 t, %1; cvt.u32.u64 %0, t; }"
        : "=r"(a) : "l"(p));
    return a;
}
__device__ __forceinline__ void cp16(uint32_t dst, const void* src) {
    asm volatile("cp.async.cg.shared.global [%0], [%1], 16;" :: "r"(dst), "l"(src));
}
#define CP_COMMIT() asm volatile("cp.async.commit_group;" ::: "memory")
#define CP_WAIT(n)  asm volatile("cp.async.wait_group %0;" :: "n"(n) : "memory")
#define SWZ(o) ((o) ^ (((o) >> 3) & 0x70))

#define LDSM_X4(r, a) \
    asm volatile("ldmatrix.sync.aligned.m8n8.x4.shared.b16 {%0,%1,%2,%3}, [%4];" \
        : "=r"((r)[0]), "=r"((r)[1]), "=r"((r)[2]), "=r"((r)[3]) : "r"(a))

__device__ __forceinline__ void mma16816(float* c, const uint32_t* a,
                                         uint32_t b0, uint32_t b1) {
    asm volatile(
        "mma.sync.aligned.m16n8k16.row.col.f32.f16.f16.f32 "
        "{%0,%1,%2,%3}, {%4,%5,%6,%7}, {%8,%9}, {%0,%1,%2,%3};"
        : "+f"(c[0]), "+f"(c[1]), "+f"(c[2]), "+f"(c[3])
        : "r"(a[0]), "r"(a[1]), "r"(a[2]), "r"(a[3]), "r"(b0), "r"(b1));
}

__device__ __forceinline__ float tanh_fast(float x) {
    float r; asm("tanh.approx.f32 %0, %1;" : "=f"(r) : "f"(x)); return r;
}
__device__ __forceinline__ float sigmoid_fast(float x) {
    return 1.0f / (1.0f + __expf(-x));
}
__device__ __forceinline__ float softplus_fast(float x) {
    if (x > 20.0f) return x;
    return __logf(1.0f + __expf(x));
}

// ---------------------------------------------------------------------------
// conversions (fp32 -> fp16)
// ---------------------------------------------------------------------------
__global__ void __launch_bounds__(256)
k_convx(const float4* __restrict__ xin, __half2* __restrict__ xb)
{
    const int n4 = MM * DM / 4;
    for (int i = blockIdx.x * 256 + threadIdx.x; i < n4; i += gridDim.x * 256) {
        float4 v = xin[i];
        xb[i * 2]     = __floats2half2_rn(v.x, v.y);
        xb[i * 2 + 1] = __floats2half2_rn(v.z, v.w);
    }
}
__global__ void __launch_bounds__(256)
k_convw(const float4* __restrict__ win, __half2* __restrict__ wb)
{
    const int i = blockIdx.x * 256 + threadIdx.x;   // covers DM*DM/4 exactly
    float4 v = win[i];
    wb[i * 2]     = __floats2half2_rn(v.x, v.y);
    wb[i * 2 + 1] = __floats2half2_rn(v.z, v.w);
}
__global__ void __launch_bounds__(256)
k_convwall(const float* __restrict__ Wd, const float* __restrict__ Wb,
           const float* __restrict__ Wc, __half2* __restrict__ wall)
{
    const int i   = blockIdx.x * 256 + threadIdx.x; // 32768 float4 slots (128 rows)
    const int row = i >> 8;
    const int k4  = i & 255;
    float4 v = make_float4(0.f, 0.f, 0.f, 0.f);
    if (row < 48) {
        const float* s = (row < 16) ? (Wd + (size_t)row * DM)
                       : (row < 32) ? (Wb + (size_t)(row - 16) * DM)
                                    : (Wc + (size_t)(row - 32) * DM);
        v = *(const float4*)(s + k4 * 4);
    }
    wall[i * 2]     = __floats2half2_rn(v.x, v.y);
    wall[i * 2 + 1] = __floats2half2_rn(v.z, v.w);
}

// ---------------------------------------------------------------------------
// fp16 mma.sync GEMM:  D[m][n] = sum_k A[m][k] * B[n][k]
// CTA tile 128x128, BK=64, 2-stage cp.async, 8 warps (2x4 grid, 64x32 tiles),
// 2 CTAs/SM (launch_bounds(256,2) -> <=128 regs).
// EPI 0: store fp16 tile to Ch.  EPI 1: abc transform (cols<48).
// ---------------------------------------------------------------------------
#define STGB 32768
#define NK   16

template<int EPI>
__global__ void __launch_bounds__(256, 2)
k_gemm(const __half* __restrict__ A, const __half* __restrict__ Bw,
       const float* __restrict__ Adiag, __half* __restrict__ Ch,
       float* __restrict__ Cf)
{
    extern __shared__ char sraw[];
    const uint32_t sb = (smem_u32(sraw) + 1023u) & ~1023u;
    const int tid = threadIdx.x, wid = tid >> 5, lane = tid & 31;
    const int wm = wid >> 2, wn = wid & 3;          // 2x4 warp grid, 64x32 each
    const int n0 = blockIdx.x * 128, m0 = blockIdx.y * 128;

    const int rr = tid >> 3, cc = tid & 7;          // 32 rows / pass
    const __half* ag = A  + (size_t)(m0 + rr) * DM + cc * 8;
    const __half* bg = Bw + (size_t)(n0 + rr) * DM + cc * 8;

    auto load_stage = [&](int slot, int k) {
        const uint32_t ab = sb + slot * STGB;
        const __half* a = ag + k * 64;
#pragma unroll
        for (int i = 0; i < 4; i++) {
            uint32_t off = (uint32_t)((rr + i * 32) * 128 + cc * 16);
            cp16(ab + SWZ(off), a + (size_t)i * 32 * DM);
        }
        const uint32_t bb2 = ab + 16384;
        const __half* b = bg + k * 64;
#pragma unroll
        for (int i = 0; i < 4; i++) {
            uint32_t off = (uint32_t)((rr + i * 32) * 128 + cc * 16);
            cp16(bb2 + SWZ(off), b + (size_t)i * 32 * DM);
        }
        CP_COMMIT();
    };

    load_stage(0, 0); load_stage(1, 1);

    float acc[4][4][4];
#pragma unroll
    for (int i = 0; i < 4; i++)
#pragma unroll
        for (int j = 0; j < 4; j++)
#pragma unroll
            for (int q = 0; q < 4; q++) acc[i][j][q] = 0.f;

    const int a_row = wm * 64 + ((lane >> 3) & 1) * 8 + (lane & 7);
    const int a_cb  = (lane >> 4) << 4;
    const int b_row = wn * 32 + ((lane >> 4) << 3) + (lane & 7);
    const int b_cb  = ((lane >> 3) & 1) << 4;

    for (int k = 0; k < NK; k++) {
        const int cur = k & 1;
        if (k < NK - 1) CP_WAIT(1); else CP_WAIT(0);
        __syncthreads();

        const uint32_t ab  = sb + cur * STGB;
        const uint32_t bb2 = ab + 16384;
#pragma unroll
        for (int kk = 0; kk < 4; kk++) {
            const int kb = kk * 32;
            uint32_t af[4][4], bf[2][4];
#pragma unroll
            for (int mi = 0; mi < 4; mi++) {
                uint32_t off = (uint32_t)((a_row + mi * 16) * 128 + kb + a_cb);
                LDSM_X4(af[mi], ab + SWZ(off));
            }
#pragma unroll
            for (int nj = 0; nj < 2; nj++) {
                uint32_t off = (uint32_t)((b_row + nj * 16) * 128 + kb + b_cb);
                LDSM_X4(bf[nj], bb2 + SWZ(off));
            }
#pragma unroll
            for (int mi = 0; mi < 4; mi++)
#pragma unroll
                for (int nj = 0; nj < 2; nj++) {
                    mma16816(acc[mi][2 * nj],     af[mi], bf[nj][0], bf[nj][1]);
                    mma16816(acc[mi][2 * nj + 1], af[mi], bf[nj][2], bf[nj][3]);
                }
        }
        __syncthreads();
        if (k + 2 < NK) load_stage(cur, k + 2);
    }

    // ------------------------------- epilogue -------------------------------
    const int g = lane >> 2, t2 = (lane & 3) * 2;
    if (EPI == 0) {
#pragma unroll
        for (int mi = 0; mi < 4; mi++) {
            const int row = m0 + wm * 64 + mi * 16 + g;
#pragma unroll
            for (int ni = 0; ni < 4; ni++) {
                const int col = n0 + wn * 32 + ni * 8 + t2;
                *(__half2*)(Ch + (size_t)row * DM + col) =
                    __floats2half2_rn(acc[mi][ni][0], acc[mi][ni][1]);
                *(__half2*)(Ch + (size_t)(row + 8) * DM + col) =
                    __floats2half2_rn(acc[mi][ni][2], acc[mi][ni][3]);
            }
        }
    } else {
#pragma unroll
        for (int mi = 0; mi < 4; mi++) {
            const int row = m0 + wm * 64 + mi * 16 + g;
#pragma unroll
            for (int ni = 0; ni < 4; ni++) {
                const int col = wn * 32 + ni * 8 + t2;
                if (col < 48) {
                    float v0 = acc[mi][ni][0], v1 = acc[mi][ni][1];
                    float v2 = acc[mi][ni][2], v3 = acc[mi][ni][3];
                    if (col < 16) {
                        const float a0 = __ldg(Adiag + col), a1 = __ldg(Adiag + col + 1);
                        v0 = __expf(softplus_fast(v0) * a0);
                        v1 = __expf(softplus_fast(v1) * a1);
                        v2 = __expf(softplus_fast(v2) * a0);
                        v3 = __expf(softplus_fast(v3) * a1);
                    }
                    float* p0 = Cf + (size_t)row * 48 + col;
                    float* p1 = Cf + (size_t)(row + 8) * 48 + col;
                    p0[0] = v0; p0[1] = v1;
                    p1[0] = v2; p1[1] = v3;
                }
            }
        }
    }
}

// ---------------------------------------------------------------------------
// LN(+bias) + sigmoid gate, xg = gate*x (fp16 in, fp16 out).
// Warp per token, 8 tokens/warp.
// ---------------------------------------------------------------------------
__global__ void __launch_bounds__(256)
k_lnxg(const __half* __restrict__ gph, const __half* __restrict__ xb,
       const float* __restrict__ bg, const float* __restrict__ lnw,
       const float* __restrict__ lnb, __half2* __restrict__ xgb)
{
    const int lane = threadIdx.x & 31;
    const int gw = (blockIdx.x * 256 + threadIdx.x) >> 5;   // 0..4095
    for (int j = 0; j < 8; j++) {
        const int t = gw + j * 4096;
        const size_t base = (size_t)t * DM;
        float4 g[8];
        float s1 = 0.f, s2 = 0.f;
#pragma unroll
        for (int i = 0; i < 8; i++) {
            const int f = i * 32 + lane;
            const __half2* gp2 = (const __half2*)(gph + base + f * 4);
            float2 p0 = __half22float2(gp2[0]);
            float2 p1 = __half22float2(gp2[1]);
            float4 b = *(const float4*)(bg + f * 4);
            float4 v = make_float4(p0.x + b.x, p0.y + b.y, p1.x + b.z, p1.y + b.w);
            g[i] = v;
            s1 += v.x + v.y + v.z + v.w;
            s2 += v.x*v.x + v.y*v.y + v.z*v.z + v.w*v.w;
        }
#pragma unroll
        for (int off = 16; off; off >>= 1) {
            s1 += __shfl_xor_sync(0xffffffffu, s1, off);
            s2 += __shfl_xor_sync(0xffffffffu, s2, off);
        }
        const float mean = s1 * (1.0f / DM);
        const float rstd = rsqrtf(s2 * (1.0f / DM) - mean * mean + LN_EPS);
#pragma unroll
        for (int i = 0; i < 8; i++) {
            const int f = i * 32 + lane;
            float4 w = *(const float4*)(lnw + f * 4);
            float4 b = *(const float4*)(lnb + f * 4);
            const __half2* xp2 = (const __half2*)(xb + base + f * 4);
            float2 x0 = __half22float2(xp2[0]);
            float2 x1 = __half22float2(xp2[1]);
            float4 v = g[i];
            float4 xg;
            xg.x = x0.x * sigmoid_fast((v.x - mean) * rstd * w.x + b.x);
            xg.y = x0.y * sigmoid_fast((v.y - mean) * rstd * w.y + b.y);
            xg.z = x1.x * sigmoid_fast((v.z - mean) * rstd * w.z + b.z);
            xg.w = x1.y * sigmoid_fast((v.w - mean) * rstd * w.w + b.w);
            xgb[(base >> 1) + f * 2]     = __floats2half2_rn(xg.x, xg.y);
            xgb[(base >> 1) + f * 2 + 1] = __floats2half2_rn(xg.z, xg.w);
        }
    }
}

// ---------------------------------------------------------------------------
// scan: one block/batch, warp0 consumes, warps1-3 prefetch (double buffer)
// ---------------------------------------------------------------------------
#define CH 128
#define NCH (TT / CH)
__global__ void __launch_bounds__(128)
k_scan(const float* __restrict__ abc, const float* __restrict__ mask,
       const float* __restrict__ h0, float* __restrict__ sout,
       float* __restrict__ out, int out_size)
{
    __shared__ float sbuf[2][CH * 48];
    __shared__ float smask[2][CH];
    const int b = blockIdx.x, tid = threadIdx.x;
    const int lane = tid & 31, warp = tid >> 5;
    const float* abc_b  = abc  + (size_t)b * TT * 48;
    const float* mask_b = mask + (size_t)b * TT;
    {
        const float4* src = (const float4*)abc_b;
        float4* dst = (float4*)sbuf[0];
        for (int i = tid; i < CH * 48 / 4; i += 128) dst[i] = src[i];
        const float4* ms = (const float4*)mask_b;
        float4* md = (float4*)smask[0];
        for (int i = tid; i < CH / 4; i += 128) md[i] = ms[i];
    }
    __syncthreads();
    float h = 0.0f;
    if (warp == 0 && lane < DS) h = h0[b * DS + lane];
    for (int c = 0; c < NCH; c++) {
        const int cur = c & 1;
        if (warp > 0 && c + 1 < NCH) {
            const int tix = tid - 32;
            const float4* src = (const float4*)(abc_b + (size_t)(c + 1) * CH * 48);
            float4* dst = (float4*)sbuf[cur ^ 1];
            for (int i = tix; i < CH * 48 / 4; i += 96) dst[i] = src[i];
            const float4* ms = (const float4*)(mask_b + (size_t)(c + 1) * CH);
            float4* md = (float4*)smask[cur ^ 1];
            for (int i = tix; i < CH / 4; i += 96) md[i] = ms[i];
        }
        if (warp == 0 && lane < DS) {
            const float* buf = sbuf[cur];
            float* sdst = sout + ((size_t)b * TT + (size_t)c * CH) * DS + lane;
#pragma unroll 4
            for (int t = 0; t < CH; t++) {
                const float a  = buf[t * 48 + lane];
                const float bb = buf[t * 48 + 16 + lane];
                const float ct = buf[t * 48 + 32 + lane];
                const float m  = smask[cur][t];
                const float hc = tanh_fast(fmaf(a, h, bb));
                h = fmaf(m, hc, (1.0f - m) * h);
                sdst[(size_t)t * DS] = ct * h;
            }
        }
        __syncthreads();
    }
    if (warp == 0 && lane < DS && out_size >= MM * DM + BB * DS)
        out[(size_t)MM * DM + b * DS + lane] = h;
}

// ---------------------------------------------------------------------------
// y = D*x + s @ W_out^T. x read as fp16 (xb). Thread t owns features 4t..4t+3.
// ---------------------------------------------------------------------------
__global__ void __launch_bounds__(256)
k_out(const float* __restrict__ sg, const __half* __restrict__ xb,
      const float* __restrict__ Wout, const float* __restrict__ Dv,
      float* __restrict__ y)
{
    const int t = threadIdx.x;
    const int d = t * 4;
    float4 wr[4][4];
#pragma unroll
    for (int r = 0; r < 4; r++)
#pragma unroll
        for (int q = 0; q < 4; q++)
            wr[r][q] = *(const float4*)(Wout + (size_t)(d + r) * DS + q * 4);
    const float4 dd = *(const float4*)(Dv + d);

    const int row0 = blockIdx.x * 16;
    for (int j = 0; j < 16; j++) {
        const int row = row0 + j;
        const float4 s0 = *(const float4*)(sg + (size_t)row * DS);
        const float4 s1 = *(const float4*)(sg + (size_t)row * DS + 4);
        const float4 s2 = *(const float4*)(sg + (size_t)row * DS + 8);
        const float4 s3 = *(const float4*)(sg + (size_t)row * DS + 12);
        float ys[4];
#pragma unroll
        for (int r = 0; r < 4; r++) {
            float a;
            a  = s0.x * wr[r][0].x + s0.y * wr[r][0].y + s0.z * wr[r][0].z + s0.w * wr[r][0].w;
            a += s1.x * wr[r][1].x + s1.y * wr[r][1].y + s1.z * wr[r][1].z + s1.w * wr[r][1].w;
            a += s2.x * wr[r][2].x + s2.y * wr[r][2].y + s2.z * wr[r][2].z + s2.w * wr[r][2].w;
            a += s3.x * wr[r][3].x + s3.y * wr[r][3].y + s3.z * wr[r][3].z + s3.w * wr[r][3].w;
            ys[r] = a;
        }
        const size_t base = (size_t)row * DM + d;
        const __half2* xp = (const __half2*)(xb + base);
        float2 x0 = __half22float2(xp[0]);
        float2 x1 = __half22float2(xp[1]);
        *(float4*)(y + base) = make_float4(ys[0] + dd.x * x0.x, ys[1] + dd.y * x0.y,
                                           ys[2] + dd.z * x1.x, ys[3] + dd.w * x1.y);
    }
}

// ---------------------------------------------------------------------------
extern "C" void kernel_launch(void* const* d_in, const int* in_sizes, int n_in,
                              void* d_out, int out_size)
{
    const float* x      = (const float*)d_in[0];
    const float* h0     = (const float*)d_in[1];
    const float* mask   = (const float*)d_in[2];
    const float* A_diag = (const float*)d_in[3];
    const float* W_del  = (const float*)d_in[4];
    const float* W_B    = (const float*)d_in[5];
    const float* W_C    = (const float*)d_in[6];
    const float* W_out  = (const float*)d_in[7];
    const float* Dv     = (const float*)d_in[8];
    const float* W_gate = (const float*)d_in[9];
    const float* b_gate = (const float*)d_in[10];
    const float* ln_w   = (const float*)d_in[11];
    const float* ln_b   = (const float*)d_in[12];
    float* out = (float*)d_out;

    float *abc, *sg;
    __half *gph, *xb, *xgb, *wb, *wall;
    cudaGetSymbolAddress((void**)&gph,  g_gph);
    cudaGetSymbolAddress((void**)&abc,  g_abc);
    cudaGetSymbolAddress((void**)&sg,   g_s);
    cudaGetSymbolAddress((void**)&xb,   g_xb);
    cudaGetSymbolAddress((void**)&xgb,  g_xgb);
    cudaGetSymbolAddress((void**)&wb,   g_wb);
    cudaGetSymbolAddress((void**)&wall, g_wall);

    const int smem_sz = 2 * STGB + 1024;    // 66560
    cudaFuncSetAttribute(k_gemm<0>, cudaFuncAttributeMaxDynamicSharedMemorySize, smem_sz);
    cudaFuncSetAttribute(k_gemm<1>, cudaFuncAttributeMaxDynamicSharedMemorySize, smem_sz);

    k_convx<<<4096, 256>>>((const float4*)x, (__half2*)xb);
    k_convw<<<1024, 256>>>((const float4*)W_gate, (__half2*)wb);
    k_convwall<<<128, 256>>>(W_del, W_B, W_C, (__half2*)wall);

    dim3 gg(DM / 128, MM / 128);            // n fastest -> A-band L2 reuse
    k_gemm<0><<<gg, 256, smem_sz>>>(xb, wb, nullptr, gph, nullptr);

    k_lnxg<<<512, 256>>>(gph, xb, b_gate, ln_w, ln_b, (__half2*)xgb);

    dim3 ga(1, MM / 128);
    k_gemm<1><<<ga, 256, smem_sz>>>(xgb, wall, A_diag, nullptr, abc);

    k_scan<<<BB, 128>>>(abc, mask, h0, sg, out, out_size);

    k_out<<<MM / 16, 256>>>(sg, xb, W_out, Dv, out);
}

// round 10
// speedup vs baseline: 4.6821x; 1.0120x over previous
#include <cuda_runtime.h>
#include <cuda_fp16.h>
#include <cstdint>

#define BB     8
#define TT     4096
#define DM     1024
#define DS     16
#define MM     (BB * TT)
#define LN_EPS 1e-5f

// ------------------------- scratch (static, no alloc) ----------------------
__device__ __half  g_gph [(size_t)MM * DM];      // gate_pre fp16 (64 MB)
__device__ __half  g_xb  [(size_t)MM * DM];      // x fp16
__device__ __half  g_xgb [(size_t)MM * DM];      // xg fp16
__device__ __half  g_wb  [DM * DM];              // W_gate fp16
__device__ __half  g_wall[128 * DM];             // Wd|Wb|Wc|pad fp16
__device__ float   g_abc [(size_t)MM * 48];      // A_bar|Bt|Ct
__device__ float   g_s   [(size_t)MM * DS];      // Ct*h

// ----------------------------- helpers -------------------------------------
__device__ __forceinline__ uint32_t smem_u32(const void* p) {
    uint32_t a;
    asm("{ .reg .u64 t; cvta.to.shared.u64 t, %1; cvt.u32.u64 %0, t; }"
        : "=r"(a) : "l"(p));
    return a;
}
__device__ __forceinline__ void cp16(uint32_t dst, const void* src) {
    asm volatile("cp.async.cg.shared.global [%0], [%1], 16;" :: "r"(dst), "l"(src));
}
#define CP_COMMIT() asm volatile("cp.async.commit_group;" ::: "memory")
#define CP_WAIT(n)  asm volatile("cp.async.wait_group %0;" :: "n"(n) : "memory")
#define SWZ(o) ((o) ^ (((o) >> 3) & 0x70))

#define LDSM_X4(r, a) \
    asm volatile("ldmatrix.sync.aligned.m8n8.x4.shared.b16 {%0,%1,%2,%3}, [%4];" \
        : "=r"((r)[0]), "=r"((r)[1]), "=r"((r)[2]), "=r"((r)[3]) : "r"(a))

__device__ __forceinline__ void mma16816(float* c, const uint32_t* a,
                                         uint32_t b0, uint32_t b1) {
    asm volatile(
        "mma.sync.aligned.m16n8k16.row.col.f32.f16.f16.f32 "
        "{%0,%1,%2,%3}, {%4,%5,%6,%7}, {%8,%9}, {%0,%1,%2,%3};"
        : "+f"(c[0]), "+f"(c[1]), "+f"(c[2]), "+f"(c[3])
        : "r"(a[0]), "r"(a[1]), "r"(a[2]), "r"(a[3]), "r"(b0), "r"(b1));
}

__device__ __forceinline__ float tanh_fast(float x) {
    float r; asm("tanh.approx.f32 %0, %1;" : "=f"(r) : "f"(x)); return r;
}
__device__ __forceinline__ float sigmoid_fast(float x) {
    return 1.0f / (1.0f + __expf(-x));
}
__device__ __forceinline__ float softplus_fast(float x) {
    if (x > 20.0f) return x;
    return __logf(1.0f + __expf(x));
}

// ---------------------------------------------------------------------------
// fused conversions (fp32 -> fp16): blocks [0,1024) W_gate, [1024,1152) wall,
// [1152,5248) x.
// ---------------------------------------------------------------------------
__global__ void __launch_bounds__(256)
k_conv(const float4* __restrict__ xin, const float4* __restrict__ win,
       const float* __restrict__ Wd, const float* __restrict__ Wb,
       const float* __restrict__ Wc,
       __half2* __restrict__ xb, __half2* __restrict__ wb,
       __half2* __restrict__ wall)
{
    const int blk = blockIdx.x;
    if (blk < 1024) {
        const int i = blk * 256 + threadIdx.x;
        float4 v = win[i];
        wb[i * 2]     = __floats2half2_rn(v.x, v.y);
        wb[i * 2 + 1] = __floats2half2_rn(v.z, v.w);
    } else if (blk < 1152) {
        const int i   = (blk - 1024) * 256 + threadIdx.x;   // 32768 slots
        const int row = i >> 8;
        const int k4  = i & 255;
        float4 v = make_float4(0.f, 0.f, 0.f, 0.f);
        if (row < 48) {
            const float* s = (row < 16) ? (Wd + (size_t)row * DM)
                           : (row < 32) ? (Wb + (size_t)(row - 16) * DM)
                                        : (Wc + (size_t)(row - 32) * DM);
            v = *(const float4*)(s + k4 * 4);
        }
        wall[i * 2]     = __floats2half2_rn(v.x, v.y);
        wall[i * 2 + 1] = __floats2half2_rn(v.z, v.w);
    } else {
        const int n4 = MM * DM / 4;
        for (int i = (blk - 1152) * 256 + threadIdx.x; i < n4; i += 4096 * 256) {
            float4 v = xin[i];
            xb[i * 2]     = __floats2half2_rn(v.x, v.y);
            xb[i * 2 + 1] = __floats2half2_rn(v.z, v.w);
        }
    }
}

// ---------------------------------------------------------------------------
// fp16 mma.sync GEMM:  D[m][n] = sum_k A[m][k] * B[n][k]
// CTA tile 128x128, BK=64, 3-stage cp.async, 8 warps (2x4 grid, 64x32 tiles),
// 2 CTAs/SM (launch_bounds(256,2) -> <=128 regs; smem 2x97KB = 194KB <= 228KB).
// EPI 0: store fp16 tile to Ch.  EPI 1: abc transform (cols<48).
// ---------------------------------------------------------------------------
#define STGB 32768
#define NK   16

template<int EPI>
__global__ void __launch_bounds__(256, 2)
k_gemm(const __half* __restrict__ A, const __half* __restrict__ Bw,
       const float* __restrict__ Adiag, __half* __restrict__ Ch,
       float* __restrict__ Cf)
{
    extern __shared__ char sraw[];
    const uint32_t sb = (smem_u32(sraw) + 1023u) & ~1023u;
    const int tid = threadIdx.x, wid = tid >> 5, lane = tid & 31;
    const int wm = wid >> 2, wn = wid & 3;          // 2x4 warp grid, 64x32 each
    const int n0 = blockIdx.x * 128, m0 = blockIdx.y * 128;

    const int rr = tid >> 3, cc = tid & 7;          // 32 rows / pass
    const __half* ag = A  + (size_t)(m0 + rr) * DM + cc * 8;
    const __half* bg = Bw + (size_t)(n0 + rr) * DM + cc * 8;

    auto load_stage = [&](int slot, int k) {
        const uint32_t ab = sb + slot * STGB;
        const __half* a = ag + k * 64;
#pragma unroll
        for (int i = 0; i < 4; i++) {
            uint32_t off = (uint32_t)((rr + i * 32) * 128 + cc * 16);
            cp16(ab + SWZ(off), a + (size_t)i * 32 * DM);
        }
        const uint32_t bb2 = ab + 16384;
        const __half* b = bg + k * 64;
#pragma unroll
        for (int i = 0; i < 4; i++) {
            uint32_t off = (uint32_t)((rr + i * 32) * 128 + cc * 16);
            cp16(bb2 + SWZ(off), b + (size_t)i * 32 * DM);
        }
        CP_COMMIT();
    };

    load_stage(0, 0); load_stage(1, 1); load_stage(2, 2);

    float acc[4][4][4];
#pragma unroll
    for (int i = 0; i < 4; i++)
#pragma unroll
        for (int j = 0; j < 4; j++)
#pragma unroll
            for (int q = 0; q < 4; q++) acc[i][j][q] = 0.f;

    const int a_row = wm * 64 + ((lane >> 3) & 1) * 8 + (lane & 7);
    const int a_cb  = (lane >> 4) << 4;
    const int b_row = wn * 32 + ((lane >> 4) << 3) + (lane & 7);
    const int b_cb  = ((lane >> 3) & 1) << 4;

    for (int k = 0; k < NK; k++) {
        const int cur = k % 3;
        if (k <= NK - 3) CP_WAIT(2); else if (k == NK - 2) CP_WAIT(1); else CP_WAIT(0);
        __syncthreads();

        const uint32_t ab  = sb + cur * STGB;
        const uint32_t bb2 = ab + 16384;
#pragma unroll
        for (int kk = 0; kk < 4; kk++) {
            const int kb = kk * 32;
            uint32_t af[4][4], bf[2][4];
#pragma unroll
            for (int mi = 0; mi < 4; mi++) {
                uint32_t off = (uint32_t)((a_row + mi * 16) * 128 + kb + a_cb);
                LDSM_X4(af[mi], ab + SWZ(off));
            }
#pragma unroll
            for (int nj = 0; nj < 2; nj++) {
                uint32_t off = (uint32_t)((b_row + nj * 16) * 128 + kb + b_cb);
                LDSM_X4(bf[nj], bb2 + SWZ(off));
            }
#pragma unroll
            for (int mi = 0; mi < 4; mi++)
#pragma unroll
                for (int nj = 0; nj < 2; nj++) {
                    mma16816(acc[mi][2 * nj],     af[mi], bf[nj][0], bf[nj][1]);
                    mma16816(acc[mi][2 * nj + 1], af[mi], bf[nj][2], bf[nj][3]);
                }
        }
        __syncthreads();
        if (k + 3 < NK) load_stage(cur, k + 3);
    }

    // ------------------------------- epilogue -------------------------------
    const int g = lane >> 2, t2 = (lane & 3) * 2;
    if (EPI == 0) {
#pragma unroll
        for (int mi = 0; mi < 4; mi++) {
            const int row = m0 + wm * 64 + mi * 16 + g;
#pragma unroll
            for (int ni = 0; ni < 4; ni++) {
                const int col = n0 + wn * 32 + ni * 8 + t2;
                *(__half2*)(Ch + (size_t)row * DM + col) =
                    __floats2half2_rn(acc[mi][ni][0], acc[mi][ni][1]);
                *(__half2*)(Ch + (size_t)(row + 8) * DM + col) =
                    __floats2half2_rn(acc[mi][ni][2], acc[mi][ni][3]);
            }
        }
    } else {
#pragma unroll
        for (int mi = 0; mi < 4; mi++) {
            const int row = m0 + wm * 64 + mi * 16 + g;
#pragma unroll
            for (int ni = 0; ni < 4; ni++) {
                const int col = wn * 32 + ni * 8 + t2;
                if (col < 48) {
                    float v0 = acc[mi][ni][0], v1 = acc[mi][ni][1];
                    float v2 = acc[mi][ni][2], v3 = acc[mi][ni][3];
                    if (col < 16) {
                        const float a0 = __ldg(Adiag + col), a1 = __ldg(Adiag + col + 1);
                        v0 = __expf(softplus_fast(v0) * a0);
                        v1 = __expf(softplus_fast(v1) * a1);
                        v2 = __expf(softplus_fast(v2) * a0);
                        v3 = __expf(softplus_fast(v3) * a1);
                    }
                    float* p0 = Cf + (size_t)row * 48 + col;
                    float* p1 = Cf + (size_t)(row + 8) * 48 + col;
                    p0[0] = v0; p0[1] = v1;
                    p1[0] = v2; p1[1] = v3;
                }
            }
        }
    }
}

// ---------------------------------------------------------------------------
// LN(+bias) + sigmoid gate, xg = gate*x (fp16 in, fp16 out).
// Warp per token, 8 tokens/warp.
// ---------------------------------------------------------------------------
__global__ void __launch_bounds__(256)
k_lnxg(const __half* __restrict__ gph, const __half* __restrict__ xb,
       const float* __restrict__ bg, const float* __restrict__ lnw,
       const float* __restrict__ lnb, __half2* __restrict__ xgb)
{
    const int lane = threadIdx.x & 31;
    const int gw = (blockIdx.x * 256 + threadIdx.x) >> 5;   // 0..4095
    for (int j = 0; j < 8; j++) {
        const int t = gw + j * 4096;
        const size_t base = (size_t)t * DM;
        float4 g[8];
        float s1 = 0.f, s2 = 0.f;
#pragma unroll
        for (int i = 0; i < 8; i++) {
            const int f = i * 32 + lane;
            const __half2* gp2 = (const __half2*)(gph + base + f * 4);
            float2 p0 = __half22float2(gp2[0]);
            float2 p1 = __half22float2(gp2[1]);
            float4 b = *(const float4*)(bg + f * 4);
            float4 v = make_float4(p0.x + b.x, p0.y + b.y, p1.x + b.z, p1.y + b.w);
            g[i] = v;
            s1 += v.x + v.y + v.z + v.w;
            s2 += v.x*v.x + v.y*v.y + v.z*v.z + v.w*v.w;
        }
#pragma unroll
        for (int off = 16; off; off >>= 1) {
            s1 += __shfl_xor_sync(0xffffffffu, s1, off);
            s2 += __shfl_xor_sync(0xffffffffu, s2, off);
        }
        const float mean = s1 * (1.0f / DM);
        const float rstd = rsqrtf(s2 * (1.0f / DM) - mean * mean + LN_EPS);
#pragma unroll
        for (int i = 0; i < 8; i++) {
            const int f = i * 32 + lane;
            float4 w = *(const float4*)(lnw + f * 4);
            float4 b = *(const float4*)(lnb + f * 4);
            const __half2* xp2 = (const __half2*)(xb + base + f * 4);
            float2 x0 = __half22float2(xp2[0]);
            float2 x1 = __half22float2(xp2[1]);
            float4 v = g[i];
            float4 xg;
            xg.x = x0.x * sigmoid_fast((v.x - mean) * rstd * w.x + b.x);
            xg.y = x0.y * sigmoid_fast((v.y - mean) * rstd * w.y + b.y);
            xg.z = x1.x * sigmoid_fast((v.z - mean) * rstd * w.z + b.z);
            xg.w = x1.y * sigmoid_fast((v.w - mean) * rstd * w.w + b.w);
            xgb[(base >> 1) + f * 2]     = __floats2half2_rn(xg.x, xg.y);
            xgb[(base >> 1) + f * 2 + 1] = __floats2half2_rn(xg.z, xg.w);
        }
    }
}

// ---------------------------------------------------------------------------
// scan: one block/batch, warp0 consumes, warps1-3 prefetch (double buffer)
// ---------------------------------------------------------------------------
#define CH 128
#define NCH (TT / CH)
__global__ void __launch_bounds__(128)
k_scan(const float* __restrict__ abc, const float* __restrict__ mask,
       const float* __restrict__ h0, float* __restrict__ sout,
       float* __restrict__ out, int out_size)
{
    __shared__ float sbuf[2][CH * 48];
    __shared__ float smask[2][CH];
    const int b = blockIdx.x, tid = threadIdx.x;
    const int lane = tid & 31, warp = tid >> 5;
    const float* abc_b  = abc  + (size_t)b * TT * 48;
    const float* mask_b = mask + (size_t)b * TT;
    {
        const float4* src = (const float4*)abc_b;
        float4* dst = (float4*)sbuf[0];
        for (int i = tid; i < CH * 48 / 4; i += 128) dst[i] = src[i];
        const float4* ms = (const float4*)mask_b;
        float4* md = (float4*)smask[0];
        for (int i = tid; i < CH / 4; i += 128) md[i] = ms[i];
    }
    __syncthreads();
    float h = 0.0f;
    if (warp == 0 && lane < DS) h = h0[b * DS + lane];
    for (int c = 0; c < NCH; c++) {
        const int cur = c & 1;
        if (warp > 0 && c + 1 < NCH) {
            const int tix = tid - 32;
            const float4* src = (const float4*)(abc_b + (size_t)(c + 1) * CH * 48);
            float4* dst = (float4*)sbuf[cur ^ 1];
            for (int i = tix; i < CH * 48 / 4; i += 96) dst[i] = src[i];
            const float4* ms = (const float4*)(mask_b + (size_t)(c + 1) * CH);
            float4* md = (float4*)smask[cur ^ 1];
            for (int i = tix; i < CH / 4; i += 96) md[i] = ms[i];
        }
        if (warp == 0 && lane < DS) {
            const float* buf = sbuf[cur];
            float* sdst = sout + ((size_t)b * TT + (size_t)c * CH) * DS + lane;
#pragma unroll 4
            for (int t = 0; t < CH; t++) {
                const float a  = buf[t * 48 + lane];
                const float bb = buf[t * 48 + 16 + lane];
                const float ct = buf[t * 48 + 32 + lane];
                const float m  = smask[cur][t];
                const float hc = tanh_fast(fmaf(a, h, bb));
                h = fmaf(m, hc, (1.0f - m) * h);
                sdst[(size_t)t * DS] = ct * h;
            }
        }
        __syncthreads();
    }
    if (warp == 0 && lane < DS && out_size >= MM * DM + BB * DS)
        out[(size_t)MM * DM + b * DS + lane] = h;
}

// ---------------------------------------------------------------------------
// y = D*x + s @ W_out^T. x read as fp16 (xb). Thread t owns features 4t..4t+3.
// ---------------------------------------------------------------------------
__global__ void __launch_bounds__(256)
k_out(const float* __restrict__ sg, const __half* __restrict__ xb,
      const float* __restrict__ Wout, const float* __restrict__ Dv,
      float* __restrict__ y)
{
    const int t = threadIdx.x;
    const int d = t * 4;
    float4 wr[4][4];
#pragma unroll
    for (int r = 0; r < 4; r++)
#pragma unroll
        for (int q = 0; q < 4; q++)
            wr[r][q] = *(const float4*)(Wout + (size_t)(d + r) * DS + q * 4);
    const float4 dd = *(const float4*)(Dv + d);

    const int row0 = blockIdx.x * 16;
    for (int j = 0; j < 16; j++) {
        const int row = row0 + j;
        const float4 s0 = *(const float4*)(sg + (size_t)row * DS);
        const float4 s1 = *(const float4*)(sg + (size_t)row * DS + 4);
        const float4 s2 = *(const float4*)(sg + (size_t)row * DS + 8);
        const float4 s3 = *(const float4*)(sg + (size_t)row * DS + 12);
        float ys[4];
#pragma unroll
        for (int r = 0; r < 4; r++) {
            float a;
            a  = s0.x * wr[r][0].x + s0.y * wr[r][0].y + s0.z * wr[r][0].z + s0.w * wr[r][0].w;
            a += s1.x * wr[r][1].x + s1.y * wr[r][1].y + s1.z * wr[r][1].z + s1.w * wr[r][1].w;
            a += s2.x * wr[r][2].x + s2.y * wr[r][2].y + s2.z * wr[r][2].z + s2.w * wr[r][2].w;
            a += s3.x * wr[r][3].x + s3.y * wr[r][3].y + s3.z * wr[r][3].z + s3.w * wr[r][3].w;
            ys[r] = a;
        }
        const size_t base = (size_t)row * DM + d;
        const __half2* xp = (const __half2*)(xb + base);
        float2 x0 = __half22float2(xp[0]);
        float2 x1 = __half22float2(xp[1]);
        *(float4*)(y + base) = make_float4(ys[0] + dd.x * x0.x, ys[1] + dd.y * x0.y,
                                           ys[2] + dd.z * x1.x, ys[3] + dd.w * x1.y);
    }
}

// ---------------------------------------------------------------------------
extern "C" void kernel_launch(void* const* d_in, const int* in_sizes, int n_in,
                              void* d_out, int out_size)
{
    const float* x      = (const float*)d_in[0];
    const float* h0     = (const float*)d_in[1];
    const float* mask   = (const float*)d_in[2];
    const float* A_diag = (const float*)d_in[3];
    const float* W_del  = (const float*)d_in[4];
    const float* W_B    = (const float*)d_in[5];
    const float* W_C    = (const float*)d_in[6];
    const float* W_out  = (const float*)d_in[7];
    const float* Dv     = (const float*)d_in[8];
    const float* W_gate = (const float*)d_in[9];
    const float* b_gate = (const float*)d_in[10];
    const float* ln_w   = (const float*)d_in[11];
    const float* ln_b   = (const float*)d_in[12];
    float* out = (float*)d_out;

    float *abc, *sg;
    __half *gph, *xb, *xgb, *wb, *wall;
    cudaGetSymbolAddress((void**)&gph,  g_gph);
    cudaGetSymbolAddress((void**)&abc,  g_abc);
    cudaGetSymbolAddress((void**)&sg,   g_s);
    cudaGetSymbolAddress((void**)&xb,   g_xb);
    cudaGetSymbolAddress((void**)&xgb,  g_xgb);
    cudaGetSymbolAddress((void**)&wb,   g_wb);
    cudaGetSymbolAddress((void**)&wall, g_wall);

    const int smem_sz = 3 * STGB + 1024;    // 99328; x2 CTAs = 194 KB/SM
    cudaFuncSetAttribute(k_gemm<0>, cudaFuncAttributeMaxDynamicSharedMemorySize, smem_sz);
    cudaFuncSetAttribute(k_gemm<1>, cudaFuncAttributeMaxDynamicSharedMemorySize, smem_sz);

    k_conv<<<5248, 256>>>((const float4*)x, (const float4*)W_gate,
                          W_del, W_B, W_C,
                          (__half2*)xb, (__half2*)wb, (__half2*)wall);

    dim3 gg(DM / 128, MM / 128);            // n fastest -> A-band L2 reuse
    k_gemm<0><<<gg, 256, smem_sz>>>(xb, wb, nullptr, gph, nullptr);

    k_lnxg<<<512, 256>>>(gph, xb, b_gate, ln_w, ln_b, (__half2*)xgb);

    dim3 ga(1, MM / 128);
    k_gemm<1><<<ga, 256, smem_sz>>>(xgb, wall, A_diag, nullptr, abc);

    k_scan<<<BB, 128>>>(abc, mask, h0, sg, out, out_size);

    k_out<<<MM / 16, 256>>>(sg, xb, W_out, Dv, out);
}

// round 11
// speedup vs baseline: 5.9944x; 1.2803x over previous
#include <cuda_runtime.h>
#include <cuda_fp16.h>
#include <cstdint>

#define BB     8
#define TT     4096
#define DM     1024
#define DS     16
#define MM     (BB * TT)
#define LN_EPS 1e-5f

// ------------------------- scratch (static, no alloc) ----------------------
__device__ __half  g_gph [(size_t)MM * DM];      // gate_pre fp16 (64 MB)
__device__ __half  g_xb  [(size_t)MM * DM];      // x fp16
__device__ __half  g_xgb [(size_t)MM * DM];      // xg fp16
__device__ __half  g_wb  [DM * DM];              // W_gate fp16
__device__ __half  g_wall[128 * DM];             // Wd|Wb|Wc|pad fp16
__device__ __half  g_prm [3 * DM];               // bg|lnw|lnb fp16
__device__ float   g_abc [(size_t)MM * 48];      // A_bar|Bt|Ct
__device__ float   g_s   [(size_t)MM * DS];      // Ct*h

// ----------------------------- helpers -------------------------------------
__device__ __forceinline__ uint32_t smem_u32(const void* p) {
    uint32_t a;
    asm("{ .reg .u64 t; cvta.to.shared.u64 t, %1; cvt.u32.u64 %0, t; }"
        : "=r"(a) : "l"(p));
    return a;
}
__device__ __forceinline__ void cp16(uint32_t dst, const void* src) {
    asm volatile("cp.async.cg.shared.global [%0], [%1], 16;" :: "r"(dst), "l"(src));
}
#define CP_COMMIT() asm volatile("cp.async.commit_group;" ::: "memory")
#define CP_WAIT(n)  asm volatile("cp.async.wait_group %0;" :: "n"(n) : "memory")
#define SWZ(o) ((o) ^ (((o) >> 3) & 0x70))

#define LDSM_X4(r, a) \
    asm volatile("ldmatrix.sync.aligned.m8n8.x4.shared.b16 {%0,%1,%2,%3}, [%4];" \
        : "=r"((r)[0]), "=r"((r)[1]), "=r"((r)[2]), "=r"((r)[3]) : "r"(a))

__device__ __forceinline__ void mma16816(float* c, const uint32_t* a,
                                         uint32_t b0, uint32_t b1) {
    asm volatile(
        "mma.sync.aligned.m16n8k16.row.col.f32.f16.f16.f32 "
        "{%0,%1,%2,%3}, {%4,%5,%6,%7}, {%8,%9}, {%0,%1,%2,%3};"
        : "+f"(c[0]), "+f"(c[1]), "+f"(c[2]), "+f"(c[3])
        : "r"(a[0]), "r"(a[1]), "r"(a[2]), "r"(a[3]), "r"(b0), "r"(b1));
}

__device__ __forceinline__ float tanh_fast(float x) {
    float r; asm("tanh.approx.f32 %0, %1;" : "=f"(r) : "f"(x)); return r;
}
__device__ __forceinline__ float sigmoid_fast(float x) {
    return 1.0f / (1.0f + __expf(-x));
}
__device__ __forceinline__ float softplus_fast(float x) {
    if (x > 20.0f) return x;
    return __logf(1.0f + __expf(x));
}

// ---------------------------------------------------------------------------
// fused conversions (fp32 -> fp16). 4 contiguous-coalesced f4 per thread.
// blocks: [0,8192) x ; [8192,8448) W_gate ; [8448,8480) wall ; 8480 params
// ---------------------------------------------------------------------------
__global__ void __launch_bounds__(256)
k_conv(const float4* __restrict__ xin, const float4* __restrict__ win,
       const float* __restrict__ Wd, const float* __restrict__ Wb,
       const float* __restrict__ Wc,
       const float* __restrict__ bg, const float* __restrict__ lnw,
       const float* __restrict__ lnb,
       __half2* __restrict__ xb, __half2* __restrict__ wb,
       __half2* __restrict__ wall, __half2* __restrict__ prm)
{
    const int blk = blockIdx.x, tid = threadIdx.x;
    if (blk < 8192) {
        const int base = blk * 1024 + tid;
#pragma unroll
        for (int k = 0; k < 4; k++) {
            const int i = base + k * 256;
            float4 v = xin[i];
            xb[i * 2]     = __floats2half2_rn(v.x, v.y);
            xb[i * 2 + 1] = __floats2half2_rn(v.z, v.w);
        }
    } else if (blk < 8448) {
        const int base = (blk - 8192) * 1024 + tid;
#pragma unroll
        for (int k = 0; k < 4; k++) {
            const int i = base + k * 256;
            float4 v = win[i];
            wb[i * 2]     = __floats2half2_rn(v.x, v.y);
            wb[i * 2 + 1] = __floats2half2_rn(v.z, v.w);
        }
    } else if (blk < 8480) {
        const int base = (blk - 8448) * 1024 + tid;
#pragma unroll
        for (int k = 0; k < 4; k++) {
            const int i = base + k * 256;       // 0..32767
            const int row = i >> 8, k4 = i & 255;
            float4 v = make_float4(0.f, 0.f, 0.f, 0.f);
            if (row < 48) {
                const float* s = (row < 16) ? (Wd + (size_t)row * DM)
                               : (row < 32) ? (Wb + (size_t)(row - 16) * DM)
                                            : (Wc + (size_t)(row - 32) * DM);
                v = *(const float4*)(s + k4 * 4);
            }
            wall[i * 2]     = __floats2half2_rn(v.x, v.y);
            wall[i * 2 + 1] = __floats2half2_rn(v.z, v.w);
        }
    } else {
#pragma unroll
        for (int k = 0; k < 3; k++) {
            const int i = k * 256 + tid;        // 0..767 float4 slots
            const float* s = (i < 256) ? bg : (i < 512) ? lnw : lnb;
            float4 v = *(const float4*)(s + (i & 255) * 4);
            prm[i * 2]     = __floats2half2_rn(v.x, v.y);
            prm[i * 2 + 1] = __floats2half2_rn(v.z, v.w);
        }
    }
}

// ---------------------------------------------------------------------------
// fp16 mma.sync GEMM (unchanged R10 config: 3-stage, 2 CTAs/SM)
// ---------------------------------------------------------------------------
#define STGB 32768
#define NK   16

template<int EPI>
__global__ void __launch_bounds__(256, 2)
k_gemm(const __half* __restrict__ A, const __half* __restrict__ Bw,
       const float* __restrict__ Adiag, __half* __restrict__ Ch,
       float* __restrict__ Cf)
{
    extern __shared__ char sraw[];
    const uint32_t sb = (smem_u32(sraw) + 1023u) & ~1023u;
    const int tid = threadIdx.x, wid = tid >> 5, lane = tid & 31;
    const int wm = wid >> 2, wn = wid & 3;
    const int n0 = blockIdx.x * 128, m0 = blockIdx.y * 128;

    const int rr = tid >> 3, cc = tid & 7;
    const __half* ag = A  + (size_t)(m0 + rr) * DM + cc * 8;
    const __half* bg = Bw + (size_t)(n0 + rr) * DM + cc * 8;

    auto load_stage = [&](int slot, int k) {
        const uint32_t ab = sb + slot * STGB;
        const __half* a = ag + k * 64;
#pragma unroll
        for (int i = 0; i < 4; i++) {
            uint32_t off = (uint32_t)((rr + i * 32) * 128 + cc * 16);
            cp16(ab + SWZ(off), a + (size_t)i * 32 * DM);
        }
        const uint32_t bb2 = ab + 16384;
        const __half* b = bg + k * 64;
#pragma unroll
        for (int i = 0; i < 4; i++) {
            uint32_t off = (uint32_t)((rr + i * 32) * 128 + cc * 16);
            cp16(bb2 + SWZ(off), b + (size_t)i * 32 * DM);
        }
        CP_COMMIT();
    };

    load_stage(0, 0); load_stage(1, 1); load_stage(2, 2);

    float acc[4][4][4];
#pragma unroll
    for (int i = 0; i < 4; i++)
#pragma unroll
        for (int j = 0; j < 4; j++)
#pragma unroll
            for (int q = 0; q < 4; q++) acc[i][j][q] = 0.f;

    const int a_row = wm * 64 + ((lane >> 3) & 1) * 8 + (lane & 7);
    const int a_cb  = (lane >> 4) << 4;
    const int b_row = wn * 32 + ((lane >> 4) << 3) + (lane & 7);
    const int b_cb  = ((lane >> 3) & 1) << 4;

    for (int k = 0; k < NK; k++) {
        const int cur = k % 3;
        if (k <= NK - 3) CP_WAIT(2); else if (k == NK - 2) CP_WAIT(1); else CP_WAIT(0);
        __syncthreads();

        const uint32_t ab  = sb + cur * STGB;
        const uint32_t bb2 = ab + 16384;
#pragma unroll
        for (int kk = 0; kk < 4; kk++) {
            const int kb = kk * 32;
            uint32_t af[4][4], bf[2][4];
#pragma unroll
            for (int mi = 0; mi < 4; mi++) {
                uint32_t off = (uint32_t)((a_row + mi * 16) * 128 + kb + a_cb);
                LDSM_X4(af[mi], ab + SWZ(off));
            }
#pragma unroll
            for (int nj = 0; nj < 2; nj++) {
                uint32_t off = (uint32_t)((b_row + nj * 16) * 128 + kb + b_cb);
                LDSM_X4(bf[nj], bb2 + SWZ(off));
            }
#pragma unroll
            for (int mi = 0; mi < 4; mi++)
#pragma unroll
                for (int nj = 0; nj < 2; nj++) {
                    mma16816(acc[mi][2 * nj],     af[mi], bf[nj][0], bf[nj][1]);
                    mma16816(acc[mi][2 * nj + 1], af[mi], bf[nj][2], bf[nj][3]);
                }
        }
        __syncthreads();
        if (k + 3 < NK) load_stage(cur, k + 3);
    }

    const int g = lane >> 2, t2 = (lane & 3) * 2;
    if (EPI == 0) {
#pragma unroll
        for (int mi = 0; mi < 4; mi++) {
            const int row = m0 + wm * 64 + mi * 16 + g;
#pragma unroll
            for (int ni = 0; ni < 4; ni++) {
                const int col = n0 + wn * 32 + ni * 8 + t2;
                *(__half2*)(Ch + (size_t)row * DM + col) =
                    __floats2half2_rn(acc[mi][ni][0], acc[mi][ni][1]);
                *(__half2*)(Ch + (size_t)(row + 8) * DM + col) =
                    __floats2half2_rn(acc[mi][ni][2], acc[mi][ni][3]);
            }
        }
    } else {
#pragma unroll
        for (int mi = 0; mi < 4; mi++) {
            const int row = m0 + wm * 64 + mi * 16 + g;
#pragma unroll
            for (int ni = 0; ni < 4; ni++) {
                const int col = wn * 32 + ni * 8 + t2;
                if (col < 48) {
                    float v0 = acc[mi][ni][0], v1 = acc[mi][ni][1];
                    float v2 = acc[mi][ni][2], v3 = acc[mi][ni][3];
                    if (col < 16) {
                        const float a0 = __ldg(Adiag + col), a1 = __ldg(Adiag + col + 1);
                        v0 = __expf(softplus_fast(v0) * a0);
                        v1 = __expf(softplus_fast(v1) * a1);
                        v2 = __expf(softplus_fast(v2) * a0);
                        v3 = __expf(softplus_fast(v3) * a1);
                    }
                    float* p0 = Cf + (size_t)row * 48 + col;
                    float* p1 = Cf + (size_t)(row + 8) * 48 + col;
                    p0[0] = v0; p0[1] = v1;
                    p1[0] = v2; p1[1] = v3;
                }
            }
        }
    }
}

// ---------------------------------------------------------------------------
// LN(+bias) + sigmoid gate, xg = gate*x. Warp per token, 16-byte loads,
// values held in regs across both passes. prm = bg|lnw|lnb fp16.
// ---------------------------------------------------------------------------
__global__ void __launch_bounds__(256)
k_lnxg(const __half* __restrict__ gph, const __half* __restrict__ xb,
       const __half* __restrict__ prm, __half* __restrict__ xgb)
{
    const int lane = threadIdx.x & 31;
    const int t = blockIdx.x * 8 + (threadIdx.x >> 5);   // token 0..32767
    const size_t base = (size_t)t * DM;

    float v[4][8];
    float s1 = 0.f, s2 = 0.f;
#pragma unroll
    for (int i = 0; i < 4; i++) {
        const int f8 = i * 256 + lane * 8;
        uint4 gv = *(const uint4*)(gph + base + f8);
        uint4 bv = *(const uint4*)(prm + f8);
        const __half2* gh = (const __half2*)&gv;
        const __half2* bh = (const __half2*)&bv;
#pragma unroll
        for (int q = 0; q < 4; q++) {
            float2 gg = __half22float2(gh[q]);
            float2 bb = __half22float2(bh[q]);
            float a0 = gg.x + bb.x, a1 = gg.y + bb.y;
            v[i][2 * q] = a0; v[i][2 * q + 1] = a1;
            s1 += a0 + a1;
            s2 += a0 * a0 + a1 * a1;
        }
    }
#pragma unroll
    for (int off = 16; off; off >>= 1) {
        s1 += __shfl_xor_sync(0xffffffffu, s1, off);
        s2 += __shfl_xor_sync(0xffffffffu, s2, off);
    }
    const float mean = s1 * (1.0f / DM);
    const float rstd = rsqrtf(s2 * (1.0f / DM) - mean * mean + LN_EPS);

#pragma unroll
    for (int i = 0; i < 4; i++) {
        const int f8 = i * 256 + lane * 8;
        uint4 xv = *(const uint4*)(xb + base + f8);
        uint4 wv = *(const uint4*)(prm + DM + f8);
        uint4 lv = *(const uint4*)(prm + 2 * DM + f8);
        const __half2* xh = (const __half2*)&xv;
        const __half2* wh = (const __half2*)&wv;
        const __half2* lh = (const __half2*)&lv;
        uint4 ov;
        __half2* oh = (__half2*)&ov;
#pragma unroll
        for (int q = 0; q < 4; q++) {
            float2 xx = __half22float2(xh[q]);
            float2 ww = __half22float2(wh[q]);
            float2 ll = __half22float2(lh[q]);
            float g0 = xx.x * sigmoid_fast((v[i][2*q]   - mean) * rstd * ww.x + ll.x);
            float g1 = xx.y * sigmoid_fast((v[i][2*q+1] - mean) * rstd * ww.y + ll.y);
            oh[q] = __floats2half2_rn(g0, g1);
        }
        *(uint4*)(xgb + base + f8) = ov;
    }
}

// ---------------------------------------------------------------------------
// scan: one block/batch, warp0 consumes, warps1-3 prefetch (double buffer)
// ---------------------------------------------------------------------------
#define CH 128
#define NCH (TT / CH)
__global__ void __launch_bounds__(128)
k_scan(const float* __restrict__ abc, const float* __restrict__ mask,
       const float* __restrict__ h0, float* __restrict__ sout,
       float* __restrict__ out, int out_size)
{
    __shared__ float sbuf[2][CH * 48];
    __shared__ float smask[2][CH];
    const int b = blockIdx.x, tid = threadIdx.x;
    const int lane = tid & 31, warp = tid >> 5;
    const float* abc_b  = abc  + (size_t)b * TT * 48;
    const float* mask_b = mask + (size_t)b * TT;
    {
        const float4* src = (const float4*)abc_b;
        float4* dst = (float4*)sbuf[0];
        for (int i = tid; i < CH * 48 / 4; i += 128) dst[i] = src[i];
        const float4* ms = (const float4*)mask_b;
        float4* md = (float4*)smask[0];
        for (int i = tid; i < CH / 4; i += 128) md[i] = ms[i];
    }
    __syncthreads();
    float h = 0.0f;
    if (warp == 0 && lane < DS) h = h0[b * DS + lane];
    for (int c = 0; c < NCH; c++) {
        const int cur = c & 1;
        if (warp > 0 && c + 1 < NCH) {
            const int tix = tid - 32;
            const float4* src = (const float4*)(abc_b + (size_t)(c + 1) * CH * 48);
            float4* dst = (float4*)sbuf[cur ^ 1];
            for (int i = tix; i < CH * 48 / 4; i += 96) dst[i] = src[i];
            const float4* ms = (const float4*)(mask_b + (size_t)(c + 1) * CH);
            float4* md = (float4*)smask[cur ^ 1];
            for (int i = tix; i < CH / 4; i += 96) md[i] = ms[i];
        }
        if (warp == 0 && lane < DS) {
            const float* buf = sbuf[cur];
            float* sdst = sout + ((size_t)b * TT + (size_t)c * CH) * DS + lane;
#pragma unroll 4
            for (int t = 0; t < CH; t++) {
                const float a  = buf[t * 48 + lane];
                const float bb = buf[t * 48 + 16 + lane];
                const float ct = buf[t * 48 + 32 + lane];
                const float m  = smask[cur][t];
                const float hc = tanh_fast(fmaf(a, h, bb));
                h = fmaf(m, hc, (1.0f - m) * h);
                sdst[(size_t)t * DS] = ct * h;
            }
        }
        __syncthreads();
    }
    if (warp == 0 && lane < DS && out_size >= MM * DM + BB * DS)
        out[(size_t)MM * DM + b * DS + lane] = h;
}

// ---------------------------------------------------------------------------
// y = D*x + s @ W_out^T. sg staged in smem; x loaded as 8B; W_out in regs.
// Block handles 16 tokens.
// ---------------------------------------------------------------------------
__global__ void __launch_bounds__(256)
k_out(const float* __restrict__ sg, const __half* __restrict__ xb,
      const float* __restrict__ Wout, const float* __restrict__ Dv,
      float* __restrict__ y)
{
    __shared__ float s_s[16 * DS];
    const int t = threadIdx.x;
    const int d = t * 4;
    const int row0 = blockIdx.x * 16;

    if (t < 64)
        ((float4*)s_s)[t] = ((const float4*)(sg + (size_t)row0 * DS))[t];

    float4 wr[4][4];
#pragma unroll
    for (int r = 0; r < 4; r++)
#pragma unroll
        for (int q = 0; q < 4; q++)
            wr[r][q] = *(const float4*)(Wout + (size_t)(d + r) * DS + q * 4);
    const float4 dd = *(const float4*)(Dv + d);
    __syncthreads();

#pragma unroll 4
    for (int j = 0; j < 16; j++) {
        const float4* sv = (const float4*)(s_s + j * DS);
        const float4 s0 = sv[0], s1 = sv[1], s2 = sv[2], s3 = sv[3];
        float ys[4];
#pragma unroll
        for (int r = 0; r < 4; r++) {
            float a;
            a  = s0.x * wr[r][0].x + s0.y * wr[r][0].y + s0.z * wr[r][0].z + s0.w * wr[r][0].w;
            a += s1.x * wr[r][1].x + s1.y * wr[r][1].y + s1.z * wr[r][1].z + s1.w * wr[r][1].w;
            a += s2.x * wr[r][2].x + s2.y * wr[r][2].y + s2.z * wr[r][2].z + s2.w * wr[r][2].w;
            a += s3.x * wr[r][3].x + s3.y * wr[r][3].y + s3.z * wr[r][3].z + s3.w * wr[r][3].w;
            ys[r] = a;
        }
        const size_t base = (size_t)(row0 + j) * DM + d;
        uint2 xu = *(const uint2*)(xb + base);
        float2 x0 = __half22float2(*(__half2*)&xu.x);
        float2 x1 = __half22float2(*(__half2*)&xu.y);
        *(float4*)(y + base) = make_float4(ys[0] + dd.x * x0.x, ys[1] + dd.y * x0.y,
                                           ys[2] + dd.z * x1.x, ys[3] + dd.w * x1.y);
    }
}

// ---------------------------------------------------------------------------
extern "C" void kernel_launch(void* const* d_in, const int* in_sizes, int n_in,
                              void* d_out, int out_size)
{
    const float* x      = (const float*)d_in[0];
    const float* h0     = (const float*)d_in[1];
    const float* mask   = (const float*)d_in[2];
    const float* A_diag = (const float*)d_in[3];
    const float* W_del  = (const float*)d_in[4];
    const float* W_B    = (const float*)d_in[5];
    const float* W_C    = (const float*)d_in[6];
    const float* W_out  = (const float*)d_in[7];
    const float* Dv     = (const float*)d_in[8];
    const float* W_gate = (const float*)d_in[9];
    const float* b_gate = (const float*)d_in[10];
    const float* ln_w   = (const float*)d_in[11];
    const float* ln_b   = (const float*)d_in[12];
    float* out = (float*)d_out;

    float *abc, *sg;
    __half *gph, *xb, *xgb, *wb, *wall, *prm;
    cudaGetSymbolAddress((void**)&gph,  g_gph);
    cudaGetSymbolAddress((void**)&abc,  g_abc);
    cudaGetSymbolAddress((void**)&sg,   g_s);
    cudaGetSymbolAddress((void**)&xb,   g_xb);
    cudaGetSymbolAddress((void**)&xgb,  g_xgb);
    cudaGetSymbolAddress((void**)&wb,   g_wb);
    cudaGetSymbolAddress((void**)&wall, g_wall);
    cudaGetSymbolAddress((void**)&prm,  g_prm);

    const int smem_sz = 3 * STGB + 1024;    // 99328; x2 CTAs = 194 KB/SM
    cudaFuncSetAttribute(k_gemm<0>, cudaFuncAttributeMaxDynamicSharedMemorySize, smem_sz);
    cudaFuncSetAttribute(k_gemm<1>, cudaFuncAttributeMaxDynamicSharedMemorySize, smem_sz);

    k_conv<<<8481, 256>>>((const float4*)x, (const float4*)W_gate,
                          W_del, W_B, W_C, b_gate, ln_w, ln_b,
                          (__half2*)xb, (__half2*)wb,
                          (__half2*)wall, (__half2*)prm);

    dim3 gg(DM / 128, MM / 128);
    k_gemm<0><<<gg, 256, smem_sz>>>(xb, wb, nullptr, gph, nullptr);

    k_lnxg<<<MM / 8, 256>>>(gph, xb, prm, xgb);

    dim3 ga(1, MM / 128);
    k_gemm<1><<<ga, 256, smem_sz>>>(xgb, wall, A_diag, nullptr, abc);

    k_scan<<<BB, 128>>>(abc, mask, h0, sg, out, out_size);

    k_out<<<MM / 16, 256>>>(sg, xb, W_out, Dv, out);
}